// round 13
// baseline (speedup 1.0000x reference)
#include <cuda_runtime.h>
#include <cuda_bf16.h>
#include <math.h>
#include <stdint.h>

#define Bsz   2
#define Lsz   2048
#define DM    768
#define DI    1536
#define NST   16
#define DTR   48
#define XDBLW 80          // DTR + 2*NST
#define MROWS (Bsz*Lsz)   // 4096
#define NC    16          // scan chunks
#define CLEN  (Lsz/NC)    // 128
#define KDT   64          // padded K for dt GEMM
#define XSPK  8           // x_proj split-K
#define NDBLK (DI/128)    // 12 scan d-blocks
#define FLAGN (Bsz * NDBLK * NC)   // 384

typedef __nv_bfloat16 bf16;

// ---------------- scratch (device globals; no allocs allowed) ----------------
__device__ bf16  g_xz  [MROWS * 2 * DI];       // in_proj output: u_raw | z (bf16)
__device__ bf16  g_ubf [MROWS * DI];           // post conv+silu (bf16)
__device__ float g_xdbl[MROWS * XDBLW];        // dtl | B | C (fp32, scan B/C)
__device__ float g_xpp [XSPK * MROWS * XDBLW]; // x_proj split-K partials
__device__ bf16  g_dtbf[MROWS * DI];           // softplus(dt) (bf16)
__device__ bf16  g_ybf [MROWS * DI];           // gated scan output (bf16)
__device__ float g_opp [2 * MROWS * DM];       // out_proj split-K partials
__device__ float g_cE  [Bsz * NC * DI * NST];  // per-chunk E
__device__ float g_cH  [Bsz * NC * DI * NST];  // per-chunk H (from h0=0)
__device__ int   g_flags[FLAGN];               // scan lookback flags
// bf16 mirrors for tensor-core GEMM operands
__device__ bf16 g_xbf   [MROWS * DM];          // x
__device__ bf16 g_xdblbf[MROWS * XDBLW];       // xdbl
__device__ bf16 g_wip   [2 * DI * DM];         // in_proj_w
__device__ bf16 g_wxp   [XDBLW * DI];          // x_proj_w
__device__ bf16 g_wdt   [DI * KDT];            // dt_proj_w zero-padded 48->64
__device__ bf16 g_wop   [DM * DI];             // out_proj_w

// ---------------- helpers ----------------------------------------------------
__device__ __forceinline__ void mma_bf16(float* c, const uint32_t* a, const uint32_t* b) {
    asm volatile(
        "mma.sync.aligned.m16n8k16.row.col.f32.bf16.bf16.f32 "
        "{%0,%1,%2,%3}, {%4,%5,%6,%7}, {%8,%9}, {%0,%1,%2,%3};\n"
        : "+f"(c[0]), "+f"(c[1]), "+f"(c[2]), "+f"(c[3])
        : "r"(a[0]), "r"(a[1]), "r"(a[2]), "r"(a[3]), "r"(b[0]), "r"(b[1]));
}

__device__ __forceinline__ void ldsm4(uint32_t* r, uint32_t addr) {
    asm volatile("ldmatrix.sync.aligned.m8n8.x4.shared.b16 {%0,%1,%2,%3}, [%4];"
                 : "=r"(r[0]), "=r"(r[1]), "=r"(r[2]), "=r"(r[3]) : "r"(addr));
}

__device__ __forceinline__ float fsilu(float x) {
    return x * __fdividef(1.f, 1.f + __expf(-x));
}

__device__ __forceinline__ void cp16u(uint32_t sdst, const void* gsrc, bool pred) {
    int sz = pred ? 16 : 0;                       // src-size 0 -> zero-fill
    asm volatile("cp.async.cg.shared.global [%0], [%1], 16, %2;\n"
                 :: "r"(sdst), "l"(gsrc), "r"(sz));
}
__device__ __forceinline__ void cp_commit() { asm volatile("cp.async.commit_group;\n"); }
template<int N_>
__device__ __forceinline__ void cp_wait() { asm volatile("cp.async.wait_group %0;\n" :: "n"(N_)); }

// ---------------- fused fp32 -> bf16 conversion + flag reset ------------------
__device__ __forceinline__ void cvt2(const float* __restrict__ s, bf16* __restrict__ d, int i) {
    float2 v = ((const float2*)s)[i];
    ((__nv_bfloat162*)d)[i] = __float22bfloat162_rn(v);
}

#define CN0 (MROWS * DM / 2)              // x
#define CN1 (CN0 + DI * DM)               // + in_proj_w
#define CN2 (CN1 + XDBLW * DI / 2)        // + x_proj_w
#define CN3 (CN2 + DM * DI / 2)           // + out_proj_w
#define CN4 (CN3 + DI * 32)               // + dt pad units
#define CN5 (CN4 + FLAGN)                 // + scan flags

__global__ void convert_all_kernel(const float* __restrict__ x,
                                   const float* __restrict__ wip_f,
                                   const float* __restrict__ wxp_f,
                                   const float* __restrict__ wop_f,
                                   const float* __restrict__ wdt_f,
                                   bf16* __restrict__ xbf, bf16* __restrict__ wip,
                                   bf16* __restrict__ wxp, bf16* __restrict__ wop,
                                   bf16* __restrict__ wdt, int* __restrict__ flags) {
    int i = blockIdx.x * blockDim.x + threadIdx.x;
    if (i < CN0)      cvt2(x, xbf, i);
    else if (i < CN1) cvt2(wip_f, wip, i - CN0);
    else if (i < CN2) cvt2(wxp_f, wxp, i - CN1);
    else if (i < CN3) cvt2(wop_f, wop, i - CN2);
    else if (i < CN4) {
        int j = i - CN3;                  // unit over DI x 32 (pairs of cols)
        int r = j >> 5, c2 = j & 31;
        float v0 = 0.f, v1 = 0.f;
        if (c2 < 24) { v0 = wdt_f[r * DTR + 2 * c2]; v1 = wdt_f[r * DTR + 2 * c2 + 1]; }
        ((__nv_bfloat162*)wdt)[r * 32 + c2] = __float22bfloat162_rn(make_float2(v0, v1));
    } else if (i < CN5) flags[i - CN4] = 0;
}

// ---------------- pipelined bf16 HMMA GEMM (ldmatrix, BK=64, 3-stage) ---------
// Single __syncthreads per mainloop iteration (classic multistage invariant).
#define SPB   72                 // smem row pitch in bf16 (64 data + 8 pad)
#define NSTG  3
#define ASTG  (128 * SPB * 2)    // 18432 bytes per stage per array
#define GSMEM (2 * NSTG * ASTG)  // 110592 bytes total

template<int EPI, int SPLITK, int OBF>
__global__ __launch_bounds__(256, 2)
void gemm_bf16_kernel(const bf16* __restrict__ A, int lda,
                      const bf16* __restrict__ W, int ldw,
                      const float* __restrict__ bias,
                      void* __restrict__ Cv,
                      int M, int N, int K) {
    extern __shared__ char dsm[];
    const uint32_t smemu = (uint32_t)__cvta_generic_to_shared(dsm);
    const int tx   = threadIdx.x;
    const int lane = tx & 31;
    const int wid  = tx >> 5;
    const int warp_m = wid & 3;
    const int warp_n = wid >> 2;
    const int brow = blockIdx.y * 128;
    const int bcol = blockIdx.x * 128;
    const int q = lane & 3;
    const int g = lane >> 2;

    const int kn = K / SPLITK;
    const int kBegin = blockIdx.z * kn;
    const int KT = kn / 64;

    int rS[4], eS[4];
#pragma unroll
    for (int i = 0; i < 4; i++) {
        int c = tx + i * 256;
        rS[i] = c >> 3;
        eS[i] = (c & 7) << 3;
    }

    uint32_t offA[2];
#pragma unroll
    for (int i = 0; i < 2; i++)
        offA[i] = (uint32_t)(((warp_m * 32 + i * 16 + (lane & 15)) * SPB
                              + ((lane >> 4) << 3)) * 2);
    uint32_t offB[4];
#pragma unroll
    for (int jj = 0; jj < 4; jj++)
        offB[jj] = (uint32_t)(((warp_n * 64 + jj * 16 + (lane & 7) + ((lane >> 4) << 3)) * SPB
                               + (((lane >> 3) & 1) << 3)) * 2);

    float acc[2][8][4];
#pragma unroll
    for (int i = 0; i < 2; i++)
#pragma unroll
        for (int j = 0; j < 8; j++)
#pragma unroll
            for (int v = 0; v < 4; v++) acc[i][j][v] = 0.f;

    auto stage = [&](int kt) {
        int st = kt % NSTG;
        uint32_t ab = smemu + st * ASTG;
        uint32_t bb = smemu + NSTG * ASTG + st * ASTG;
        int k0 = kBegin + kt * 64;
#pragma unroll
        for (int i = 0; i < 4; i++) {
            cp16u(ab + (uint32_t)((rS[i] * SPB + eS[i]) * 2),
                  A + (size_t)(brow + rS[i]) * lda + k0 + eS[i], true);
            cp16u(bb + (uint32_t)((rS[i] * SPB + eS[i]) * 2),
                  W + (size_t)(bcol + rS[i]) * ldw + k0 + eS[i], (bcol + rS[i]) < N);
        }
        cp_commit();
    };

#pragma unroll
    for (int s = 0; s < NSTG - 1; s++) {
        if (s < KT) stage(s); else cp_commit();
    }

    for (int kt = 0; kt < KT; kt++) {
        cp_wait<NSTG - 2>();
        __syncthreads();
        const int st = kt % NSTG;
        const uint32_t ab = smemu + st * ASTG;
        const uint32_t bb = smemu + NSTG * ASTG + st * ASTG;
#pragma unroll
        for (int kk = 0; kk < 64; kk += 16) {
            uint32_t af[2][4], bfr[4][4];
            ldsm4(af[0], ab + offA[0] + kk * 2);
            ldsm4(af[1], ab + offA[1] + kk * 2);
#pragma unroll
            for (int jj = 0; jj < 4; jj++)
                ldsm4(bfr[jj], bb + offB[jj] + kk * 2);
#pragma unroll
            for (int i = 0; i < 2; i++)
#pragma unroll
                for (int j = 0; j < 8; j++) {
                    const uint32_t* bp = &bfr[j >> 1][(j & 1) << 1];
                    mma_bf16(acc[i][j], af[i], bp);
                }
        }
        // buffer (kt+NSTG-1)%NSTG was consumed at iteration kt-1; the sync at
        // the top of this iteration proves all warps finished it -> safe.
        if (kt + NSTG - 1 < KT) stage(kt + NSTG - 1); else cp_commit();
    }

    // epilogue
    float* Cf = (float*)Cv + (size_t)blockIdx.z * M * N;
    bf16*  Cb = (bf16*)Cv;
#pragma unroll
    for (int i = 0; i < 2; i++) {
#pragma unroll
        for (int j = 0; j < 8; j++) {
            int r0w = brow + warp_m * 32 + i * 16 + g;
            int c0w = bcol + warp_n * 64 + j * 8 + 2 * q;
            if (c0w >= N) continue;
            float v0 = acc[i][j][0], v1 = acc[i][j][1];
            float v2 = acc[i][j][2], v3 = acc[i][j][3];
            if (EPI == 1) {
                float b0 = bias[c0w], b1 = bias[c0w + 1];
                v0 += b0; v1 += b1; v2 += b0; v3 += b1;
                v0 = (v0 > 15.f) ? v0 : __logf(1.f + __expf(v0));
                v1 = (v1 > 15.f) ? v1 : __logf(1.f + __expf(v1));
                v2 = (v2 > 15.f) ? v2 : __logf(1.f + __expf(v2));
                v3 = (v3 > 15.f) ? v3 : __logf(1.f + __expf(v3));
            }
            if (OBF) {
                *(__nv_bfloat162*)(Cb + (size_t)r0w * N + c0w) =
                    __float22bfloat162_rn(make_float2(v0, v1));
                *(__nv_bfloat162*)(Cb + (size_t)(r0w + 8) * N + c0w) =
                    __float22bfloat162_rn(make_float2(v2, v3));
            } else {
                *(float2*)(Cf + (size_t)r0w * N + c0w)       = make_float2(v0, v1);
                *(float2*)(Cf + (size_t)(r0w + 8) * N + c0w) = make_float2(v2, v3);
            }
        }
    }
}

// ---------------- x_proj split-K reduce (fp32 + bf16 outputs) ----------------
__global__ void xp_reduce_kernel(const float* __restrict__ p,
                                 float* __restrict__ o,
                                 bf16* __restrict__ obf) {
    int i = blockIdx.x * blockDim.x + threadIdx.x;
    const int S = MROWS * XDBLW;
    if (i >= S) return;
    float v = 0.f;
#pragma unroll
    for (int k = 0; k < XSPK; k++) v += p[i + (size_t)k * S];
    o[i] = v;
    obf[i] = __float2bfloat16(v);
}

// ---------------- causal depthwise conv (k=4) + bias + SiLU ------------------
__global__ __launch_bounds__(256)
void conv_silu_kernel(const bf16* __restrict__ xz,
                      const float* __restrict__ cw,
                      const float* __restrict__ cb,
                      bf16* __restrict__ u) {
    const int lane = threadIdx.x & 31;
    const int w    = threadIdx.x >> 5;
    const int d  = blockIdx.x * 32 + lane;
    const int l0 = (blockIdx.y * 8 + w) * 8;
    const int b  = blockIdx.z;

    float4 wk = ((const float4*)cw)[d];
    float bias = cb[d];

    float xv[11];
#pragma unroll
    for (int i = 0; i < 11; i++) {
        int ls = l0 - 3 + i;
        xv[i] = (ls >= 0)
            ? __bfloat162float(xz[(size_t)(b * Lsz + ls) * (2 * DI) + d]) : 0.f;
    }
#pragma unroll
    for (int j = 0; j < 8; j++) {
        float acc = bias;
        acc = fmaf(wk.x, xv[j],     acc);
        acc = fmaf(wk.y, xv[j + 1], acc);
        acc = fmaf(wk.z, xv[j + 2], acc);
        acc = fmaf(wk.w, xv[j + 3], acc);
        u[(size_t)(b * Lsz + l0 + j) * DI + d] = __float2bfloat16(fsilu(acc));
    }
}

// ---------------- scan: shared pieces ----------------------------------------
__device__ __forceinline__ void compute_e(float e[NST], float dtv,
                                          const float A[NST], bool fast) {
    if (fast) {
        float p  = __expf(-dtv);
        float p2 = p * p, p4 = p2 * p2, p8 = p4 * p4;
        e[0]  = p;        e[1]  = p2;       e[2]  = p2 * p;   e[3]  = p4;
        e[4]  = p4 * p;   e[5]  = p4 * p2;  e[6]  = p4 * e[2];e[7]  = p8;
        e[8]  = p8 * p;   e[9]  = p8 * p2;  e[10] = p8 * e[2];e[11] = p8 * p4;
        e[12] = p8 * e[4];e[13] = p8 * e[5];e[14] = p8 * e[6];e[15] = p8 * p8;
    } else {
#pragma unroll
        for (int n = 0; n < NST; n++) e[n] = __expf(dtv * A[n]);
    }
}

__device__ __forceinline__ bool load_A(float A[NST], const float* __restrict__ A_log, int d) {
    bool fast = true;
#pragma unroll
    for (int n = 0; n < NST; n++) {
        A[n] = -expf(A_log[d * NST + n]);
        fast = fast && (fabsf(A[n] + (float)(n + 1)) <= 1e-3f * (float)(n + 1));
    }
    return fast;
}

// ---------------- fused selective scan (decoupled lookback) -------------------
// Phase A: local scan from h0=0, y_local = C.h_local + D*u (bf16 in smem);
// publish (E, H) + flag. Fold: wait predecessors, h0 = fold(E_i, H_i).
// Correction: y = (y_local + C.(P_t o h0)) * silu(z), P_t = exp(A * prefix dt).
#define SCAN_SMEM (CLEN * 32 * 4 + CLEN * 128 * 2)   // 16KB + 32KB = 49152

__global__ __launch_bounds__(128)
void scan_fused_kernel(const bf16* __restrict__ dt,
                       const bf16* __restrict__ u,
                       const float* __restrict__ xdbl,
                       const bf16* __restrict__ xz,
                       const float* __restrict__ A_log,
                       const float* __restrict__ Dv,
                       float* __restrict__ cE,
                       float* __restrict__ cH,
                       int* __restrict__ flags,
                       bf16* __restrict__ ybf) {
    extern __shared__ char sm[];
    float* sBC = (float*)sm;                        // CLEN*32 fp32
    bf16*  yloc = (bf16*)(sm + CLEN * 32 * 4);      // CLEN*128 bf16
    const int tid = threadIdx.x;
    const int d = blockIdx.x * 128 + tid;
    const int c = blockIdx.y;
    const int b = blockIdx.z;
    const int row0 = b * Lsz + c * CLEN;
    const int fbase = (b * NDBLK + blockIdx.x) * NC;

    for (int i = tid; i < CLEN * 32; i += 128)
        sBC[i] = xdbl[(size_t)(row0 + (i >> 5)) * XDBLW + DTR + (i & 31)];
    __syncthreads();

    float A[NST];
    bool fast = load_A(A, A_log, d);
    float h[NST];
#pragma unroll
    for (int n = 0; n < NST; n++) h[n] = 0.f;
    float sdt = 0.f;
    const float Dd = Dv[d];

    // ---- phase A: local scan ----
#pragma unroll 2
    for (int t = 0; t < CLEN; t++) {
        const int row = row0 + t;
        float dtv = __bfloat162float(dt[(size_t)row * DI + d]);
        float uv  = __bfloat162float(u [(size_t)row * DI + d]);
        float e[NST];
        compute_e(e, dtv, A, fast);
        float dtu = dtv * uv;
        sdt += dtv;
        const float* B = &sBC[t * 32];
        const float* C = &sBC[t * 32 + 16];
        float yl = Dd * uv;
#pragma unroll
        for (int n = 0; n < NST; n++) {
            h[n] = fmaf(h[n], e[n], dtu * B[n]);
            yl   = fmaf(h[n], C[n], yl);
        }
        yloc[t * 128 + tid] = __float2bfloat16(yl);
    }

    // ---- publish (E, H) + flag (threadFenceReduction pattern) ----
    {
        float E[NST];
        compute_e(E, sdt, A, fast);
        size_t base = ((size_t)(b * NC + c) * DI + d) * NST;
#pragma unroll
        for (int n = 0; n < NST; n++) { cE[base + n] = E[n]; cH[base + n] = h[n]; }
    }
    __threadfence();
    __syncthreads();
    if (tid == 0) atomicExch(&flags[fbase + c], 1);

    // ---- fold predecessors' states into h0 ----
    float h0[NST];
#pragma unroll
    for (int n = 0; n < NST; n++) h0[n] = 0.f;
    for (int i = 0; i < c; i++) {
        if (tid == 0) {
            while (atomicAdd(&flags[fbase + i], 0) == 0) __nanosleep(64);
        }
        __syncthreads();
        size_t ib = ((size_t)(b * NC + i) * DI + d) * NST;
#pragma unroll
        for (int n = 0; n < NST; n++)
            h0[n] = fmaf(cE[ib + n], h0[n], cH[ib + n]);
    }

    // ---- correction + gate ----
    float sdt2 = 0.f;
#pragma unroll 2
    for (int t = 0; t < CLEN; t++) {
        const int row = row0 + t;
        float dtv = __bfloat162float(dt[(size_t)row * DI + d]);
        sdt2 += dtv;
        float corr = 0.f;
        if (c > 0) {
            float P[NST];
            compute_e(P, sdt2, A, fast);
            const float* C = &sBC[t * 32 + 16];
#pragma unroll
            for (int n = 0; n < NST; n++)
                corr = fmaf(P[n] * h0[n], C[n], corr);
        }
        float zv = __bfloat162float(xz[(size_t)row * (2 * DI) + DI + d]);
        float yl = __bfloat162float(yloc[t * 128 + tid]);
        ybf[(size_t)row * DI + d] = __float2bfloat16((yl + corr) * fsilu(zv));
    }
}

// ---------------- out_proj partial sum + residual + LayerNorm ------------------
__global__ void ln_kernel(const float* __restrict__ pre,    // 2 partials stacked
                          const float* __restrict__ resid,
                          const float* __restrict__ w,
                          const float* __restrict__ bb,
                          float* __restrict__ out) {
    const int row = blockIdx.x;
    const int tid = threadIdx.x;
    __shared__ float vbuf[DM];
    __shared__ float ws[8], w2s[8];
    __shared__ float s_mu, s_inv;
    const size_t S = (size_t)MROWS * DM;
    float s = 0.f, s2 = 0.f;
    for (int i = tid; i < DM; i += blockDim.x) {
        size_t o = (size_t)row * DM + i;
        float v = pre[o] + pre[o + S] + resid[o];
        vbuf[i] = v;
        s += v; s2 += v * v;
    }
#pragma unroll
    for (int o = 16; o; o >>= 1) {
        s  += __shfl_xor_sync(0xffffffffu, s,  o);
        s2 += __shfl_xor_sync(0xffffffffu, s2, o);
    }
    int wid = tid >> 5, lane = tid & 31;
    if (lane == 0) { ws[wid] = s; w2s[wid] = s2; }
    __syncthreads();
    if (tid == 0) {
        float S1 = 0.f, S2 = 0.f;
        for (int i = 0; i < 8; i++) { S1 += ws[i]; S2 += w2s[i]; }
        float mu  = S1 / (float)DM;
        float var = S2 / (float)DM - mu * mu;
        s_mu = mu;
        s_inv = rsqrtf(var + 1e-5f);
    }
    __syncthreads();
    float mu = s_mu, inv = s_inv;
    for (int i = tid; i < DM; i += blockDim.x)
        out[(size_t)row * DM + i] = (vbuf[i] - mu) * inv * w[i] + bb[i];
}

// ---------------- launch ----------------------------------------------------
static float* sym_ptr(const void* symbol) {
    void* p = nullptr;
    cudaGetSymbolAddress(&p, symbol);
    return (float*)p;
}
static bf16* sym_ptr_bf(const void* symbol) {
    void* p = nullptr;
    cudaGetSymbolAddress(&p, symbol);
    return (bf16*)p;
}
static int* sym_ptr_i(const void* symbol) {
    void* p = nullptr;
    cudaGetSymbolAddress(&p, symbol);
    return (int*)p;
}

extern "C" void kernel_launch(void* const* d_in, const int* in_sizes, int n_in,
                              void* d_out, int out_size) {
    const float* x         = (const float*)d_in[0];
    const float* in_proj_w = (const float*)d_in[1];
    const float* conv_w    = (const float*)d_in[2];
    const float* conv_b    = (const float*)d_in[3];
    const float* x_proj_w  = (const float*)d_in[4];
    const float* dt_proj_w = (const float*)d_in[5];
    const float* dt_proj_b = (const float*)d_in[6];
    const float* A_log     = (const float*)d_in[7];
    const float* Dv        = (const float*)d_in[8];
    const float* out_proj_w= (const float*)d_in[9];
    const float* ln_w      = (const float*)d_in[10];
    const float* ln_b      = (const float*)d_in[11];
    float* out = (float*)d_out;

    bf16*  xz    = sym_ptr_bf(g_xz);
    bf16*  ubf   = sym_ptr_bf(g_ubf);
    float* xdbl  = sym_ptr(g_xdbl);
    float* xpp   = sym_ptr(g_xpp);
    bf16*  dtbf  = sym_ptr_bf(g_dtbf);
    bf16*  ybf   = sym_ptr_bf(g_ybf);
    float* opp   = sym_ptr(g_opp);
    float* cE    = sym_ptr(g_cE);
    float* cH    = sym_ptr(g_cH);
    int*   flags = sym_ptr_i(g_flags);
    bf16* xbf    = sym_ptr_bf(g_xbf);
    bf16* xdblbf = sym_ptr_bf(g_xdblbf);
    bf16* wip    = sym_ptr_bf(g_wip);
    bf16* wxp    = sym_ptr_bf(g_wxp);
    bf16* wdt    = sym_ptr_bf(g_wdt);
    bf16* wop    = sym_ptr_bf(g_wop);

    const int M = MROWS;

    static int attr_done = 0;
    if (!attr_done) {
        cudaFuncSetAttribute(gemm_bf16_kernel<0, 1, 1>,
                             cudaFuncAttributeMaxDynamicSharedMemorySize, GSMEM);
        cudaFuncSetAttribute(gemm_bf16_kernel<0, XSPK, 0>,
                             cudaFuncAttributeMaxDynamicSharedMemorySize, GSMEM);
        cudaFuncSetAttribute(gemm_bf16_kernel<1, 1, 1>,
                             cudaFuncAttributeMaxDynamicSharedMemorySize, GSMEM);
        cudaFuncSetAttribute(gemm_bf16_kernel<0, 2, 0>,
                             cudaFuncAttributeMaxDynamicSharedMemorySize, GSMEM);
        cudaFuncSetAttribute(scan_fused_kernel,
                             cudaFuncAttributeMaxDynamicSharedMemorySize, SCAN_SMEM);
        attr_done = 1;
    }

    // 0) conversions + flag reset in ONE kernel
    convert_all_kernel<<<(CN5 + 255) / 256, 256>>>(
        x, in_proj_w, x_proj_w, out_proj_w, dt_proj_w,
        xbf, wip, wxp, wop, wdt, flags);

    // 1) in_proj: xz[M, 3072] = x @ in_proj_w^T  (bf16 out)
    gemm_bf16_kernel<0, 1, 1><<<dim3((2 * DI) / 128, M / 128, 1), 256, GSMEM>>>(
        xbf, DM, wip, DM, nullptr, xz, M, 2 * DI, DM);

    // 2) causal depthwise conv + SiLU -> ubf
    conv_silu_kernel<<<dim3(DI / 32, Lsz / 64, Bsz), 256>>>(xz, conv_w, conv_b, ubf);

    // 3) x_proj: xdbl[M, 80] = u @ x_proj_w^T (split-K = 8)
    gemm_bf16_kernel<0, XSPK, 0><<<dim3(1, M / 128, XSPK), 256, GSMEM>>>(
        ubf, DI, wxp, DI, nullptr, xpp, M, XDBLW, DI);
    xp_reduce_kernel<<<(M * XDBLW + 255) / 256, 256>>>(xpp, xdbl, xdblbf);

    // 4) dt[M,1536] = softplus(dtl @ dt_proj_w^T + b)  (bf16 out; K padded 48->64)
    gemm_bf16_kernel<1, 1, 1><<<dim3(DI / 128, M / 128, 1), 256, GSMEM>>>(
        xdblbf, XDBLW, wdt, KDT, dt_proj_b, dtbf, M, DI, KDT);

    // 5) fused chunk-parallel selective scan + gate -> ybf
    scan_fused_kernel<<<dim3(NDBLK, NC, Bsz), 128, SCAN_SMEM>>>(
        dtbf, ubf, xdbl, xz, A_log, Dv, cE, cH, flags, ybf);

    // 6) out_proj: opp[z][M,768] = y @ out_proj_w^T (split-K = 2)
    gemm_bf16_kernel<0, 2, 0><<<dim3(DM / 128, M / 128, 2), 256, GSMEM>>>(
        ybf, DI, wop, DI, nullptr, opp, M, DM, DI);

    // 7) partial-sum + residual + LayerNorm -> d_out
    ln_kernel<<<M, 256>>>(opp, x, ln_w, ln_b, out);
}

// round 14
// speedup vs baseline: 1.0001x; 1.0001x over previous
#include <cuda_runtime.h>
#include <cuda_bf16.h>
#include <math.h>
#include <stdint.h>

#define Bsz   2
#define Lsz   2048
#define DM    768
#define DI    1536
#define NST   16
#define DTR   48
#define XDBLW 80          // DTR + 2*NST
#define MROWS (Bsz*Lsz)   // 4096
#define NC    16          // scan chunks
#define CLEN  (Lsz/NC)    // 128
#define KDT   64          // padded K for dt GEMM
#define XSPK  8           // x_proj split-K
#define NDBLK (DI/128)    // 12 scan d-blocks
#define FLAGN (Bsz * NDBLK * NC)   // 384

typedef __nv_bfloat16 bf16;

// ---------------- scratch (device globals; no allocs allowed) ----------------
__device__ bf16  g_xz  [MROWS * 2 * DI];       // in_proj output: u_raw | z (bf16)
__device__ bf16  g_ubf [MROWS * DI];           // post conv+silu (bf16)
__device__ float g_xdbl[MROWS * XDBLW];        // dtl | B | C (fp32, scan B/C)
__device__ float g_xpp [XSPK * MROWS * XDBLW]; // x_proj split-K partials
__device__ bf16  g_dtbf[MROWS * DI];           // softplus(dt) (bf16)
__device__ bf16  g_ybf [MROWS * DI];           // gated scan output (bf16)
__device__ float g_opp [2 * MROWS * DM];       // out_proj split-K partials
__device__ float g_cE  [Bsz * NC * DI * NST];  // per-chunk E
__device__ float g_cH  [Bsz * NC * DI * NST];  // per-chunk H (from h0=0)
__device__ int   g_flags[FLAGN];               // scan lookback flags
// bf16 mirrors for tensor-core GEMM operands
__device__ bf16 g_xbf   [MROWS * DM];          // x
__device__ bf16 g_xdblbf[MROWS * XDBLW];       // xdbl
__device__ bf16 g_wip   [2 * DI * DM];         // in_proj_w
__device__ bf16 g_wxp   [XDBLW * DI];          // x_proj_w
__device__ bf16 g_wdt   [DI * KDT];            // dt_proj_w zero-padded 48->64
__device__ bf16 g_wop   [DM * DI];             // out_proj_w

// ---------------- helpers ----------------------------------------------------
__device__ __forceinline__ void mma_bf16(float* c, const uint32_t* a, const uint32_t* b) {
    asm volatile(
        "mma.sync.aligned.m16n8k16.row.col.f32.bf16.bf16.f32 "
        "{%0,%1,%2,%3}, {%4,%5,%6,%7}, {%8,%9}, {%0,%1,%2,%3};\n"
        : "+f"(c[0]), "+f"(c[1]), "+f"(c[2]), "+f"(c[3])
        : "r"(a[0]), "r"(a[1]), "r"(a[2]), "r"(a[3]), "r"(b[0]), "r"(b[1]));
}

__device__ __forceinline__ void ldsm4(uint32_t* r, uint32_t addr) {
    asm volatile("ldmatrix.sync.aligned.m8n8.x4.shared.b16 {%0,%1,%2,%3}, [%4];"
                 : "=r"(r[0]), "=r"(r[1]), "=r"(r[2]), "=r"(r[3]) : "r"(addr));
}

__device__ __forceinline__ float fsilu(float x) {
    return x * __fdividef(1.f, 1.f + __expf(-x));
}

__device__ __forceinline__ void cp16u(uint32_t sdst, const void* gsrc, bool pred) {
    int sz = pred ? 16 : 0;                       // src-size 0 -> zero-fill
    asm volatile("cp.async.cg.shared.global [%0], [%1], 16, %2;\n"
                 :: "r"(sdst), "l"(gsrc), "r"(sz));
}
__device__ __forceinline__ void cp_commit() { asm volatile("cp.async.commit_group;\n"); }
template<int N_>
__device__ __forceinline__ void cp_wait() { asm volatile("cp.async.wait_group %0;\n" :: "n"(N_)); }

// ---------------- fused fp32 -> bf16 conversion + flag reset ------------------
__device__ __forceinline__ void cvt2(const float* __restrict__ s, bf16* __restrict__ d, int i) {
    float2 v = ((const float2*)s)[i];
    ((__nv_bfloat162*)d)[i] = __float22bfloat162_rn(v);
}

#define CN0 (MROWS * DM / 2)              // x
#define CN1 (CN0 + DI * DM)               // + in_proj_w
#define CN2 (CN1 + XDBLW * DI / 2)        // + x_proj_w
#define CN3 (CN2 + DM * DI / 2)           // + out_proj_w
#define CN4 (CN3 + DI * 32)               // + dt pad units
#define CN5 (CN4 + FLAGN)                 // + scan flags

__global__ void convert_all_kernel(const float* __restrict__ x,
                                   const float* __restrict__ wip_f,
                                   const float* __restrict__ wxp_f,
                                   const float* __restrict__ wop_f,
                                   const float* __restrict__ wdt_f,
                                   bf16* __restrict__ xbf, bf16* __restrict__ wip,
                                   bf16* __restrict__ wxp, bf16* __restrict__ wop,
                                   bf16* __restrict__ wdt, int* __restrict__ flags) {
    int i = blockIdx.x * blockDim.x + threadIdx.x;
    if (i < CN0)      cvt2(x, xbf, i);
    else if (i < CN1) cvt2(wip_f, wip, i - CN0);
    else if (i < CN2) cvt2(wxp_f, wxp, i - CN1);
    else if (i < CN3) cvt2(wop_f, wop, i - CN2);
    else if (i < CN4) {
        int j = i - CN3;                  // unit over DI x 32 (pairs of cols)
        int r = j >> 5, c2 = j & 31;
        float v0 = 0.f, v1 = 0.f;
        if (c2 < 24) { v0 = wdt_f[r * DTR + 2 * c2]; v1 = wdt_f[r * DTR + 2 * c2 + 1]; }
        ((__nv_bfloat162*)wdt)[r * 32 + c2] = __float22bfloat162_rn(make_float2(v0, v1));
    } else if (i < CN5) flags[i - CN4] = 0;
}

// ---------------- pipelined bf16 HMMA GEMM (ldmatrix, BK=64, 3-stage) ---------
// Single __syncthreads per mainloop iteration (classic multistage invariant).
#define SPB   72                 // smem row pitch in bf16 (64 data + 8 pad)
#define NSTG  3
#define ASTG  (128 * SPB * 2)    // 18432 bytes per stage per array
#define GSMEM (2 * NSTG * ASTG)  // 110592 bytes total

template<int EPI, int SPLITK, int OBF>
__global__ __launch_bounds__(256, 2)
void gemm_bf16_kernel(const bf16* __restrict__ A, int lda,
                      const bf16* __restrict__ W, int ldw,
                      const float* __restrict__ bias,
                      void* __restrict__ Cv,
                      int M, int N, int K) {
    extern __shared__ char dsm[];
    const uint32_t smemu = (uint32_t)__cvta_generic_to_shared(dsm);
    const int tx   = threadIdx.x;
    const int lane = tx & 31;
    const int wid  = tx >> 5;
    const int warp_m = wid & 3;
    const int warp_n = wid >> 2;
    const int brow = blockIdx.y * 128;
    const int bcol = blockIdx.x * 128;
    const int q = lane & 3;
    const int g = lane >> 2;

    const int kn = K / SPLITK;
    const int kBegin = blockIdx.z * kn;
    const int KT = kn / 64;

    int rS[4], eS[4];
#pragma unroll
    for (int i = 0; i < 4; i++) {
        int c = tx + i * 256;
        rS[i] = c >> 3;
        eS[i] = (c & 7) << 3;
    }

    uint32_t offA[2];
#pragma unroll
    for (int i = 0; i < 2; i++)
        offA[i] = (uint32_t)(((warp_m * 32 + i * 16 + (lane & 15)) * SPB
                              + ((lane >> 4) << 3)) * 2);
    uint32_t offB[4];
#pragma unroll
    for (int jj = 0; jj < 4; jj++)
        offB[jj] = (uint32_t)(((warp_n * 64 + jj * 16 + (lane & 7) + ((lane >> 4) << 3)) * SPB
                               + (((lane >> 3) & 1) << 3)) * 2);

    float acc[2][8][4];
#pragma unroll
    for (int i = 0; i < 2; i++)
#pragma unroll
        for (int j = 0; j < 8; j++)
#pragma unroll
            for (int v = 0; v < 4; v++) acc[i][j][v] = 0.f;

    auto stage = [&](int kt) {
        int st = kt % NSTG;
        uint32_t ab = smemu + st * ASTG;
        uint32_t bb = smemu + NSTG * ASTG + st * ASTG;
        int k0 = kBegin + kt * 64;
#pragma unroll
        for (int i = 0; i < 4; i++) {
            cp16u(ab + (uint32_t)((rS[i] * SPB + eS[i]) * 2),
                  A + (size_t)(brow + rS[i]) * lda + k0 + eS[i], true);
            cp16u(bb + (uint32_t)((rS[i] * SPB + eS[i]) * 2),
                  W + (size_t)(bcol + rS[i]) * ldw + k0 + eS[i], (bcol + rS[i]) < N);
        }
        cp_commit();
    };

#pragma unroll
    for (int s = 0; s < NSTG - 1; s++) {
        if (s < KT) stage(s); else cp_commit();
    }

    for (int kt = 0; kt < KT; kt++) {
        cp_wait<NSTG - 2>();
        __syncthreads();
        const int st = kt % NSTG;
        const uint32_t ab = smemu + st * ASTG;
        const uint32_t bb = smemu + NSTG * ASTG + st * ASTG;
#pragma unroll
        for (int kk = 0; kk < 64; kk += 16) {
            uint32_t af[2][4], bfr[4][4];
            ldsm4(af[0], ab + offA[0] + kk * 2);
            ldsm4(af[1], ab + offA[1] + kk * 2);
#pragma unroll
            for (int jj = 0; jj < 4; jj++)
                ldsm4(bfr[jj], bb + offB[jj] + kk * 2);
#pragma unroll
            for (int i = 0; i < 2; i++)
#pragma unroll
                for (int j = 0; j < 8; j++) {
                    const uint32_t* bp = &bfr[j >> 1][(j & 1) << 1];
                    mma_bf16(acc[i][j], af[i], bp);
                }
        }
        // buffer (kt+NSTG-1)%NSTG was consumed at iteration kt-1; the sync at
        // the top of this iteration proves all warps finished it -> safe.
        if (kt + NSTG - 1 < KT) stage(kt + NSTG - 1); else cp_commit();
    }

    // epilogue
    float* Cf = (float*)Cv + (size_t)blockIdx.z * M * N;
    bf16*  Cb = (bf16*)Cv;
#pragma unroll
    for (int i = 0; i < 2; i++) {
#pragma unroll
        for (int j = 0; j < 8; j++) {
            int r0w = brow + warp_m * 32 + i * 16 + g;
            int c0w = bcol + warp_n * 64 + j * 8 + 2 * q;
            if (c0w >= N) continue;
            float v0 = acc[i][j][0], v1 = acc[i][j][1];
            float v2 = acc[i][j][2], v3 = acc[i][j][3];
            if (EPI == 1) {
                float b0 = bias[c0w], b1 = bias[c0w + 1];
                v0 += b0; v1 += b1; v2 += b0; v3 += b1;
                v0 = (v0 > 15.f) ? v0 : __logf(1.f + __expf(v0));
                v1 = (v1 > 15.f) ? v1 : __logf(1.f + __expf(v1));
                v2 = (v2 > 15.f) ? v2 : __logf(1.f + __expf(v2));
                v3 = (v3 > 15.f) ? v3 : __logf(1.f + __expf(v3));
            }
            if (OBF) {
                *(__nv_bfloat162*)(Cb + (size_t)r0w * N + c0w) =
                    __float22bfloat162_rn(make_float2(v0, v1));
                *(__nv_bfloat162*)(Cb + (size_t)(r0w + 8) * N + c0w) =
                    __float22bfloat162_rn(make_float2(v2, v3));
            } else {
                *(float2*)(Cf + (size_t)r0w * N + c0w)       = make_float2(v0, v1);
                *(float2*)(Cf + (size_t)(r0w + 8) * N + c0w) = make_float2(v2, v3);
            }
        }
    }
}

// ---------------- x_proj split-K reduce (fp32 + bf16 outputs) ----------------
__global__ void xp_reduce_kernel(const float* __restrict__ p,
                                 float* __restrict__ o,
                                 bf16* __restrict__ obf) {
    int i = blockIdx.x * blockDim.x + threadIdx.x;
    const int S = MROWS * XDBLW;
    if (i >= S) return;
    float v = 0.f;
#pragma unroll
    for (int k = 0; k < XSPK; k++) v += p[i + (size_t)k * S];
    o[i] = v;
    obf[i] = __float2bfloat16(v);
}

// ---------------- causal depthwise conv (k=4) + bias + SiLU ------------------
__global__ __launch_bounds__(256)
void conv_silu_kernel(const bf16* __restrict__ xz,
                      const float* __restrict__ cw,
                      const float* __restrict__ cb,
                      bf16* __restrict__ u) {
    const int lane = threadIdx.x & 31;
    const int w    = threadIdx.x >> 5;
    const int d  = blockIdx.x * 32 + lane;
    const int l0 = (blockIdx.y * 8 + w) * 8;
    const int b  = blockIdx.z;

    float4 wk = ((const float4*)cw)[d];
    float bias = cb[d];

    float xv[11];
#pragma unroll
    for (int i = 0; i < 11; i++) {
        int ls = l0 - 3 + i;
        xv[i] = (ls >= 0)
            ? __bfloat162float(xz[(size_t)(b * Lsz + ls) * (2 * DI) + d]) : 0.f;
    }
#pragma unroll
    for (int j = 0; j < 8; j++) {
        float acc = bias;
        acc = fmaf(wk.x, xv[j],     acc);
        acc = fmaf(wk.y, xv[j + 1], acc);
        acc = fmaf(wk.z, xv[j + 2], acc);
        acc = fmaf(wk.w, xv[j + 3], acc);
        u[(size_t)(b * Lsz + l0 + j) * DI + d] = __float2bfloat16(fsilu(acc));
    }
}

// ---------------- scan: shared pieces ----------------------------------------
__device__ __forceinline__ void compute_e(float e[NST], float dtv,
                                          const float A[NST], bool fast) {
    if (fast) {
        float p  = __expf(-dtv);
        float p2 = p * p, p4 = p2 * p2, p8 = p4 * p4;
        e[0]  = p;        e[1]  = p2;       e[2]  = p2 * p;   e[3]  = p4;
        e[4]  = p4 * p;   e[5]  = p4 * p2;  e[6]  = p4 * e[2];e[7]  = p8;
        e[8]  = p8 * p;   e[9]  = p8 * p2;  e[10] = p8 * e[2];e[11] = p8 * p4;
        e[12] = p8 * e[4];e[13] = p8 * e[5];e[14] = p8 * e[6];e[15] = p8 * p8;
    } else {
#pragma unroll
        for (int n = 0; n < NST; n++) e[n] = __expf(dtv * A[n]);
    }
}

__device__ __forceinline__ bool load_A(float A[NST], const float* __restrict__ A_log, int d) {
    bool fast = true;
#pragma unroll
    for (int n = 0; n < NST; n++) {
        A[n] = -expf(A_log[d * NST + n]);
        fast = fast && (fabsf(A[n] + (float)(n + 1)) <= 1e-3f * (float)(n + 1));
    }
    return fast;
}

// ---------------- fused selective scan (decoupled lookback) -------------------
// Phase A: local scan from h0=0, y_local = C.h_local + D*u (bf16 in smem);
// publish (E, H) + flag. Fold: wait predecessors, h0 = fold(E_i, H_i).
// Correction: y = (y_local + C.(P_t o h0)) * silu(z), P_t = exp(A * prefix dt).
#define SCAN_SMEM (CLEN * 32 * 4 + CLEN * 128 * 2)   // 16KB + 32KB = 49152

__global__ __launch_bounds__(128)
void scan_fused_kernel(const bf16* __restrict__ dt,
                       const bf16* __restrict__ u,
                       const float* __restrict__ xdbl,
                       const bf16* __restrict__ xz,
                       const float* __restrict__ A_log,
                       const float* __restrict__ Dv,
                       float* __restrict__ cE,
                       float* __restrict__ cH,
                       int* __restrict__ flags,
                       bf16* __restrict__ ybf) {
    extern __shared__ char sm[];
    float* sBC = (float*)sm;                        // CLEN*32 fp32
    bf16*  yloc = (bf16*)(sm + CLEN * 32 * 4);      // CLEN*128 bf16
    const int tid = threadIdx.x;
    const int d = blockIdx.x * 128 + tid;
    const int c = blockIdx.y;
    const int b = blockIdx.z;
    const int row0 = b * Lsz + c * CLEN;
    const int fbase = (b * NDBLK + blockIdx.x) * NC;

    for (int i = tid; i < CLEN * 32; i += 128)
        sBC[i] = xdbl[(size_t)(row0 + (i >> 5)) * XDBLW + DTR + (i & 31)];
    __syncthreads();

    float A[NST];
    bool fast = load_A(A, A_log, d);
    float h[NST];
#pragma unroll
    for (int n = 0; n < NST; n++) h[n] = 0.f;
    float sdt = 0.f;
    const float Dd = Dv[d];

    // ---- phase A: local scan ----
#pragma unroll 2
    for (int t = 0; t < CLEN; t++) {
        const int row = row0 + t;
        float dtv = __bfloat162float(dt[(size_t)row * DI + d]);
        float uv  = __bfloat162float(u [(size_t)row * DI + d]);
        float e[NST];
        compute_e(e, dtv, A, fast);
        float dtu = dtv * uv;
        sdt += dtv;
        const float* B = &sBC[t * 32];
        const float* C = &sBC[t * 32 + 16];
        float yl = Dd * uv;
#pragma unroll
        for (int n = 0; n < NST; n++) {
            h[n] = fmaf(h[n], e[n], dtu * B[n]);
            yl   = fmaf(h[n], C[n], yl);
        }
        yloc[t * 128 + tid] = __float2bfloat16(yl);
    }

    // ---- publish (E, H) + flag (threadFenceReduction pattern) ----
    {
        float E[NST];
        compute_e(E, sdt, A, fast);
        size_t base = ((size_t)(b * NC + c) * DI + d) * NST;
#pragma unroll
        for (int n = 0; n < NST; n++) { cE[base + n] = E[n]; cH[base + n] = h[n]; }
    }
    __threadfence();
    __syncthreads();
    if (tid == 0) atomicExch(&flags[fbase + c], 1);

    // ---- fold predecessors' states into h0 ----
    float h0[NST];
#pragma unroll
    for (int n = 0; n < NST; n++) h0[n] = 0.f;
    for (int i = 0; i < c; i++) {
        if (tid == 0) {
            while (atomicAdd(&flags[fbase + i], 0) == 0) __nanosleep(64);
        }
        __syncthreads();
        size_t ib = ((size_t)(b * NC + i) * DI + d) * NST;
#pragma unroll
        for (int n = 0; n < NST; n++)
            h0[n] = fmaf(cE[ib + n], h0[n], cH[ib + n]);
    }

    // ---- correction + gate ----
    float sdt2 = 0.f;
#pragma unroll 2
    for (int t = 0; t < CLEN; t++) {
        const int row = row0 + t;
        float dtv = __bfloat162float(dt[(size_t)row * DI + d]);
        sdt2 += dtv;
        float corr = 0.f;
        if (c > 0) {
            float P[NST];
            compute_e(P, sdt2, A, fast);
            const float* C = &sBC[t * 32 + 16];
#pragma unroll
            for (int n = 0; n < NST; n++)
                corr = fmaf(P[n] * h0[n], C[n], corr);
        }
        float zv = __bfloat162float(xz[(size_t)row * (2 * DI) + DI + d]);
        float yl = __bfloat162float(yloc[t * 128 + tid]);
        ybf[(size_t)row * DI + d] = __float2bfloat16((yl + corr) * fsilu(zv));
    }
}

// ---------------- out_proj partial sum + residual + LayerNorm ------------------
__global__ void ln_kernel(const float* __restrict__ pre,    // 2 partials stacked
                          const float* __restrict__ resid,
                          const float* __restrict__ w,
                          const float* __restrict__ bb,
                          float* __restrict__ out) {
    const int row = blockIdx.x;
    const int tid = threadIdx.x;
    __shared__ float vbuf[DM];
    __shared__ float ws[8], w2s[8];
    __shared__ float s_mu, s_inv;
    const size_t S = (size_t)MROWS * DM;
    float s = 0.f, s2 = 0.f;
    for (int i = tid; i < DM; i += blockDim.x) {
        size_t o = (size_t)row * DM + i;
        float v = pre[o] + pre[o + S] + resid[o];
        vbuf[i] = v;
        s += v; s2 += v * v;
    }
#pragma unroll
    for (int o = 16; o; o >>= 1) {
        s  += __shfl_xor_sync(0xffffffffu, s,  o);
        s2 += __shfl_xor_sync(0xffffffffu, s2, o);
    }
    int wid = tid >> 5, lane = tid & 31;
    if (lane == 0) { ws[wid] = s; w2s[wid] = s2; }
    __syncthreads();
    if (tid == 0) {
        float S1 = 0.f, S2 = 0.f;
        for (int i = 0; i < 8; i++) { S1 += ws[i]; S2 += w2s[i]; }
        float mu  = S1 / (float)DM;
        float var = S2 / (float)DM - mu * mu;
        s_mu = mu;
        s_inv = rsqrtf(var + 1e-5f);
    }
    __syncthreads();
    float mu = s_mu, inv = s_inv;
    for (int i = tid; i < DM; i += blockDim.x)
        out[(size_t)row * DM + i] = (vbuf[i] - mu) * inv * w[i] + bb[i];
}

// ---------------- launch ----------------------------------------------------
static float* sym_ptr(const void* symbol) {
    void* p = nullptr;
    cudaGetSymbolAddress(&p, symbol);
    return (float*)p;
}
static bf16* sym_ptr_bf(const void* symbol) {
    void* p = nullptr;
    cudaGetSymbolAddress(&p, symbol);
    return (bf16*)p;
}
static int* sym_ptr_i(const void* symbol) {
    void* p = nullptr;
    cudaGetSymbolAddress(&p, symbol);
    return (int*)p;
}

extern "C" void kernel_launch(void* const* d_in, const int* in_sizes, int n_in,
                              void* d_out, int out_size) {
    const float* x         = (const float*)d_in[0];
    const float* in_proj_w = (const float*)d_in[1];
    const float* conv_w    = (const float*)d_in[2];
    const float* conv_b    = (const float*)d_in[3];
    const float* x_proj_w  = (const float*)d_in[4];
    const float* dt_proj_w = (const float*)d_in[5];
    const float* dt_proj_b = (const float*)d_in[6];
    const float* A_log     = (const float*)d_in[7];
    const float* Dv        = (const float*)d_in[8];
    const float* out_proj_w= (const float*)d_in[9];
    const float* ln_w      = (const float*)d_in[10];
    const float* ln_b      = (const float*)d_in[11];
    float* out = (float*)d_out;

    bf16*  xz    = sym_ptr_bf(g_xz);
    bf16*  ubf   = sym_ptr_bf(g_ubf);
    float* xdbl  = sym_ptr(g_xdbl);
    float* xpp   = sym_ptr(g_xpp);
    bf16*  dtbf  = sym_ptr_bf(g_dtbf);
    bf16*  ybf   = sym_ptr_bf(g_ybf);
    float* opp   = sym_ptr(g_opp);
    float* cE    = sym_ptr(g_cE);
    float* cH    = sym_ptr(g_cH);
    int*   flags = sym_ptr_i(g_flags);
    bf16* xbf    = sym_ptr_bf(g_xbf);
    bf16* xdblbf = sym_ptr_bf(g_xdblbf);
    bf16* wip    = sym_ptr_bf(g_wip);
    bf16* wxp    = sym_ptr_bf(g_wxp);
    bf16* wdt    = sym_ptr_bf(g_wdt);
    bf16* wop    = sym_ptr_bf(g_wop);

    const int M = MROWS;

    static int attr_done = 0;
    if (!attr_done) {
        cudaFuncSetAttribute(gemm_bf16_kernel<0, 1, 1>,
                             cudaFuncAttributeMaxDynamicSharedMemorySize, GSMEM);
        cudaFuncSetAttribute(gemm_bf16_kernel<0, XSPK, 0>,
                             cudaFuncAttributeMaxDynamicSharedMemorySize, GSMEM);
        cudaFuncSetAttribute(gemm_bf16_kernel<1, 1, 1>,
                             cudaFuncAttributeMaxDynamicSharedMemorySize, GSMEM);
        cudaFuncSetAttribute(gemm_bf16_kernel<0, 2, 0>,
                             cudaFuncAttributeMaxDynamicSharedMemorySize, GSMEM);
        cudaFuncSetAttribute(scan_fused_kernel,
                             cudaFuncAttributeMaxDynamicSharedMemorySize, SCAN_SMEM);
        attr_done = 1;
    }

    // 0) conversions + flag reset in ONE kernel
    convert_all_kernel<<<(CN5 + 255) / 256, 256>>>(
        x, in_proj_w, x_proj_w, out_proj_w, dt_proj_w,
        xbf, wip, wxp, wop, wdt, flags);

    // 1) in_proj: xz[M, 3072] = x @ in_proj_w^T  (bf16 out)
    gemm_bf16_kernel<0, 1, 1><<<dim3((2 * DI) / 128, M / 128, 1), 256, GSMEM>>>(
        xbf, DM, wip, DM, nullptr, xz, M, 2 * DI, DM);

    // 2) causal depthwise conv + SiLU -> ubf
    conv_silu_kernel<<<dim3(DI / 32, Lsz / 64, Bsz), 256>>>(xz, conv_w, conv_b, ubf);

    // 3) x_proj: xdbl[M, 80] = u @ x_proj_w^T (split-K = 8)
    gemm_bf16_kernel<0, XSPK, 0><<<dim3(1, M / 128, XSPK), 256, GSMEM>>>(
        ubf, DI, wxp, DI, nullptr, xpp, M, XDBLW, DI);
    xp_reduce_kernel<<<(M * XDBLW + 255) / 256, 256>>>(xpp, xdbl, xdblbf);

    // 4) dt[M,1536] = softplus(dtl @ dt_proj_w^T + b)  (bf16 out; K padded 48->64)
    gemm_bf16_kernel<1, 1, 1><<<dim3(DI / 128, M / 128, 1), 256, GSMEM>>>(
        xdblbf, XDBLW, wdt, KDT, dt_proj_b, dtbf, M, DI, KDT);

    // 5) fused chunk-parallel selective scan + gate -> ybf
    scan_fused_kernel<<<dim3(NDBLK, NC, Bsz), 128, SCAN_SMEM>>>(
        dtbf, ubf, xdbl, xz, A_log, Dv, cE, cH, flags, ybf);

    // 6) out_proj: opp[z][M,768] = y @ out_proj_w^T (split-K = 2)
    gemm_bf16_kernel<0, 2, 0><<<dim3(DM / 128, M / 128, 2), 256, GSMEM>>>(
        ybf, DI, wop, DI, nullptr, opp, M, DM, DI);

    // 7) partial-sum + residual + LayerNorm -> d_out
    ln_kernel<<<M, 256>>>(opp, x, ln_w, ln_b, out);
}

// round 15
// speedup vs baseline: 1.0009x; 1.0008x over previous
#include <cuda_runtime.h>
#include <cuda_bf16.h>
#include <math.h>
#include <stdint.h>

#define Bsz   2
#define Lsz   2048
#define DM    768
#define DI    1536
#define NST   16
#define DTR   48
#define XDBLW 80          // DTR + 2*NST
#define MROWS (Bsz*Lsz)   // 4096
#define NC    16          // scan chunks
#define CLEN  (Lsz/NC)    // 128
#define KDT   64          // padded K for dt GEMM
#define XSPK  8           // x_proj split-K
#define NDBLK (DI/128)    // 12 scan d-blocks
#define FLAGN (Bsz * NDBLK * NC)   // 384

typedef __nv_bfloat16 bf16;

// ---------------- scratch (device globals; no allocs allowed) ----------------
__device__ bf16  g_xz  [MROWS * 2 * DI];       // in_proj output: u_raw | z (bf16)
__device__ bf16  g_ubf [MROWS * DI];           // post conv+silu (bf16)
__device__ float g_xdbl[MROWS * XDBLW];        // dtl | B | C (fp32, scan B/C)
__device__ float g_xpp [XSPK * MROWS * XDBLW]; // x_proj split-K partials
__device__ bf16  g_dtbf[MROWS * DI];           // softplus(dt) (bf16)
__device__ bf16  g_ybf [MROWS * DI];           // gated scan output (bf16)
__device__ float g_opp [2 * MROWS * DM];       // out_proj split-K partials
__device__ float g_cE  [Bsz * NC * DI * NST];  // per-chunk E
__device__ float g_cH  [Bsz * NC * DI * NST];  // per-chunk H (from h0=0)
__device__ int   g_flags[FLAGN];               // scan lookback flags
// bf16 mirrors for tensor-core GEMM operands
__device__ bf16 g_xbf   [MROWS * DM];          // x
__device__ bf16 g_xdblbf[MROWS * XDBLW];       // xdbl
__device__ bf16 g_wip   [2 * DI * DM];         // in_proj_w
__device__ bf16 g_wxp   [XDBLW * DI];          // x_proj_w
__device__ bf16 g_wdt   [DI * KDT];            // dt_proj_w zero-padded 48->64
__device__ bf16 g_wop   [DM * DI];             // out_proj_w

// ---------------- helpers ----------------------------------------------------
__device__ __forceinline__ void mma_bf16(float* c, const uint32_t* a, const uint32_t* b) {
    asm volatile(
        "mma.sync.aligned.m16n8k16.row.col.f32.bf16.bf16.f32 "
        "{%0,%1,%2,%3}, {%4,%5,%6,%7}, {%8,%9}, {%0,%1,%2,%3};\n"
        : "+f"(c[0]), "+f"(c[1]), "+f"(c[2]), "+f"(c[3])
        : "r"(a[0]), "r"(a[1]), "r"(a[2]), "r"(a[3]), "r"(b[0]), "r"(b[1]));
}

__device__ __forceinline__ void ldsm4(uint32_t* r, uint32_t addr) {
    asm volatile("ldmatrix.sync.aligned.m8n8.x4.shared.b16 {%0,%1,%2,%3}, [%4];"
                 : "=r"(r[0]), "=r"(r[1]), "=r"(r[2]), "=r"(r[3]) : "r"(addr));
}

__device__ __forceinline__ float fsilu(float x) {
    return x * __fdividef(1.f, 1.f + __expf(-x));
}

__device__ __forceinline__ void cp16u(uint32_t sdst, const void* gsrc, bool pred) {
    int sz = pred ? 16 : 0;                       // src-size 0 -> zero-fill
    asm volatile("cp.async.cg.shared.global [%0], [%1], 16, %2;\n"
                 :: "r"(sdst), "l"(gsrc), "r"(sz));
}
__device__ __forceinline__ void cp_commit() { asm volatile("cp.async.commit_group;\n"); }
template<int N_>
__device__ __forceinline__ void cp_wait() { asm volatile("cp.async.wait_group %0;\n" :: "n"(N_)); }

// ---------------- fused fp32 -> bf16 conversion + flag reset ------------------
__device__ __forceinline__ void cvt2(const float* __restrict__ s, bf16* __restrict__ d, int i) {
    float2 v = ((const float2*)s)[i];
    ((__nv_bfloat162*)d)[i] = __float22bfloat162_rn(v);
}

#define CN0 (MROWS * DM / 2)              // x
#define CN1 (CN0 + DI * DM)               // + in_proj_w
#define CN2 (CN1 + XDBLW * DI / 2)        // + x_proj_w
#define CN3 (CN2 + DM * DI / 2)           // + out_proj_w
#define CN4 (CN3 + DI * 32)               // + dt pad units
#define CN5 (CN4 + FLAGN)                 // + scan flags

__global__ void convert_all_kernel(const float* __restrict__ x,
                                   const float* __restrict__ wip_f,
                                   const float* __restrict__ wxp_f,
                                   const float* __restrict__ wop_f,
                                   const float* __restrict__ wdt_f,
                                   bf16* __restrict__ xbf, bf16* __restrict__ wip,
                                   bf16* __restrict__ wxp, bf16* __restrict__ wop,
                                   bf16* __restrict__ wdt, int* __restrict__ flags) {
    int i = blockIdx.x * blockDim.x + threadIdx.x;
    if (i < CN0)      cvt2(x, xbf, i);
    else if (i < CN1) cvt2(wip_f, wip, i - CN0);
    else if (i < CN2) cvt2(wxp_f, wxp, i - CN1);
    else if (i < CN3) cvt2(wop_f, wop, i - CN2);
    else if (i < CN4) {
        int j = i - CN3;                  // unit over DI x 32 (pairs of cols)
        int r = j >> 5, c2 = j & 31;
        float v0 = 0.f, v1 = 0.f;
        if (c2 < 24) { v0 = wdt_f[r * DTR + 2 * c2]; v1 = wdt_f[r * DTR + 2 * c2 + 1]; }
        ((__nv_bfloat162*)wdt)[r * 32 + c2] = __float22bfloat162_rn(make_float2(v0, v1));
    } else if (i < CN5) flags[i - CN4] = 0;
}

// ---------------- pipelined bf16 HMMA GEMM (ldmatrix, BK=64, 3-stage) ---------
// Single __syncthreads per mainloop iteration (classic multistage invariant).
#define SPB   72                 // smem row pitch in bf16 (64 data + 8 pad)
#define NSTG  3
#define ASTG  (128 * SPB * 2)    // 18432 bytes per stage per array
#define GSMEM (2 * NSTG * ASTG)  // 110592 bytes total

template<int EPI, int SPLITK, int OBF>
__global__ __launch_bounds__(256, 2)
void gemm_bf16_kernel(const bf16* __restrict__ A, int lda,
                      const bf16* __restrict__ W, int ldw,
                      const float* __restrict__ bias,
                      void* __restrict__ Cv,
                      int M, int N, int K) {
    extern __shared__ char dsm[];
    const uint32_t smemu = (uint32_t)__cvta_generic_to_shared(dsm);
    const int tx   = threadIdx.x;
    const int lane = tx & 31;
    const int wid  = tx >> 5;
    const int warp_m = wid & 3;
    const int warp_n = wid >> 2;
    const int brow = blockIdx.y * 128;
    const int bcol = blockIdx.x * 128;
    const int q = lane & 3;
    const int g = lane >> 2;

    const int kn = K / SPLITK;
    const int kBegin = blockIdx.z * kn;
    const int KT = kn / 64;

    int rS[4], eS[4];
#pragma unroll
    for (int i = 0; i < 4; i++) {
        int c = tx + i * 256;
        rS[i] = c >> 3;
        eS[i] = (c & 7) << 3;
    }

    uint32_t offA[2];
#pragma unroll
    for (int i = 0; i < 2; i++)
        offA[i] = (uint32_t)(((warp_m * 32 + i * 16 + (lane & 15)) * SPB
                              + ((lane >> 4) << 3)) * 2);
    uint32_t offB[4];
#pragma unroll
    for (int jj = 0; jj < 4; jj++)
        offB[jj] = (uint32_t)(((warp_n * 64 + jj * 16 + (lane & 7) + ((lane >> 4) << 3)) * SPB
                               + (((lane >> 3) & 1) << 3)) * 2);

    float acc[2][8][4];
#pragma unroll
    for (int i = 0; i < 2; i++)
#pragma unroll
        for (int j = 0; j < 8; j++)
#pragma unroll
            for (int v = 0; v < 4; v++) acc[i][j][v] = 0.f;

    auto stage = [&](int kt) {
        int st = kt % NSTG;
        uint32_t ab = smemu + st * ASTG;
        uint32_t bb = smemu + NSTG * ASTG + st * ASTG;
        int k0 = kBegin + kt * 64;
#pragma unroll
        for (int i = 0; i < 4; i++) {
            cp16u(ab + (uint32_t)((rS[i] * SPB + eS[i]) * 2),
                  A + (size_t)(brow + rS[i]) * lda + k0 + eS[i], true);
            cp16u(bb + (uint32_t)((rS[i] * SPB + eS[i]) * 2),
                  W + (size_t)(bcol + rS[i]) * ldw + k0 + eS[i], (bcol + rS[i]) < N);
        }
        cp_commit();
    };

#pragma unroll
    for (int s = 0; s < NSTG - 1; s++) {
        if (s < KT) stage(s); else cp_commit();
    }

    for (int kt = 0; kt < KT; kt++) {
        cp_wait<NSTG - 2>();
        __syncthreads();
        const int st = kt % NSTG;
        const uint32_t ab = smemu + st * ASTG;
        const uint32_t bb = smemu + NSTG * ASTG + st * ASTG;
#pragma unroll
        for (int kk = 0; kk < 64; kk += 16) {
            uint32_t af[2][4], bfr[4][4];
            ldsm4(af[0], ab + offA[0] + kk * 2);
            ldsm4(af[1], ab + offA[1] + kk * 2);
#pragma unroll
            for (int jj = 0; jj < 4; jj++)
                ldsm4(bfr[jj], bb + offB[jj] + kk * 2);
#pragma unroll
            for (int i = 0; i < 2; i++)
#pragma unroll
                for (int j = 0; j < 8; j++) {
                    const uint32_t* bp = &bfr[j >> 1][(j & 1) << 1];
                    mma_bf16(acc[i][j], af[i], bp);
                }
        }
        // buffer (kt+NSTG-1)%NSTG was consumed at iteration kt-1; the sync at
        // the top of this iteration proves all warps finished it -> safe.
        if (kt + NSTG - 1 < KT) stage(kt + NSTG - 1); else cp_commit();
    }

    // epilogue
    float* Cf = (float*)Cv + (size_t)blockIdx.z * M * N;
    bf16*  Cb = (bf16*)Cv;
#pragma unroll
    for (int i = 0; i < 2; i++) {
#pragma unroll
        for (int j = 0; j < 8; j++) {
            int r0w = brow + warp_m * 32 + i * 16 + g;
            int c0w = bcol + warp_n * 64 + j * 8 + 2 * q;
            if (c0w >= N) continue;
            float v0 = acc[i][j][0], v1 = acc[i][j][1];
            float v2 = acc[i][j][2], v3 = acc[i][j][3];
            if (EPI == 1) {
                float b0 = bias[c0w], b1 = bias[c0w + 1];
                v0 += b0; v1 += b1; v2 += b0; v3 += b1;
                v0 = (v0 > 15.f) ? v0 : __logf(1.f + __expf(v0));
                v1 = (v1 > 15.f) ? v1 : __logf(1.f + __expf(v1));
                v2 = (v2 > 15.f) ? v2 : __logf(1.f + __expf(v2));
                v3 = (v3 > 15.f) ? v3 : __logf(1.f + __expf(v3));
            }
            if (OBF) {
                *(__nv_bfloat162*)(Cb + (size_t)r0w * N + c0w) =
                    __float22bfloat162_rn(make_float2(v0, v1));
                *(__nv_bfloat162*)(Cb + (size_t)(r0w + 8) * N + c0w) =
                    __float22bfloat162_rn(make_float2(v2, v3));
            } else {
                *(float2*)(Cf + (size_t)r0w * N + c0w)       = make_float2(v0, v1);
                *(float2*)(Cf + (size_t)(r0w + 8) * N + c0w) = make_float2(v2, v3);
            }
        }
    }
}

// ---------------- x_proj split-K reduce (fp32 + bf16 outputs) ----------------
__global__ void xp_reduce_kernel(const float* __restrict__ p,
                                 float* __restrict__ o,
                                 bf16* __restrict__ obf) {
    int i = blockIdx.x * blockDim.x + threadIdx.x;
    const int S = MROWS * XDBLW;
    if (i >= S) return;
    float v = 0.f;
#pragma unroll
    for (int k = 0; k < XSPK; k++) v += p[i + (size_t)k * S];
    o[i] = v;
    obf[i] = __float2bfloat16(v);
}

// ---------------- causal depthwise conv (k=4) + bias + SiLU ------------------
__global__ __launch_bounds__(256)
void conv_silu_kernel(const bf16* __restrict__ xz,
                      const float* __restrict__ cw,
                      const float* __restrict__ cb,
                      bf16* __restrict__ u) {
    const int lane = threadIdx.x & 31;
    const int w    = threadIdx.x >> 5;
    const int d  = blockIdx.x * 32 + lane;
    const int l0 = (blockIdx.y * 8 + w) * 8;
    const int b  = blockIdx.z;

    float4 wk = ((const float4*)cw)[d];
    float bias = cb[d];

    float xv[11];
#pragma unroll
    for (int i = 0; i < 11; i++) {
        int ls = l0 - 3 + i;
        xv[i] = (ls >= 0)
            ? __bfloat162float(xz[(size_t)(b * Lsz + ls) * (2 * DI) + d]) : 0.f;
    }
#pragma unroll
    for (int j = 0; j < 8; j++) {
        float acc = bias;
        acc = fmaf(wk.x, xv[j],     acc);
        acc = fmaf(wk.y, xv[j + 1], acc);
        acc = fmaf(wk.z, xv[j + 2], acc);
        acc = fmaf(wk.w, xv[j + 3], acc);
        u[(size_t)(b * Lsz + l0 + j) * DI + d] = __float2bfloat16(fsilu(acc));
    }
}

// ---------------- scan: shared pieces ----------------------------------------
__device__ __forceinline__ void compute_e(float e[NST], float dtv,
                                          const float A[NST], bool fast) {
    if (fast) {
        float p  = __expf(-dtv);
        float p2 = p * p, p4 = p2 * p2, p8 = p4 * p4;
        e[0]  = p;        e[1]  = p2;       e[2]  = p2 * p;   e[3]  = p4;
        e[4]  = p4 * p;   e[5]  = p4 * p2;  e[6]  = p4 * e[2];e[7]  = p8;
        e[8]  = p8 * p;   e[9]  = p8 * p2;  e[10] = p8 * e[2];e[11] = p8 * p4;
        e[12] = p8 * e[4];e[13] = p8 * e[5];e[14] = p8 * e[6];e[15] = p8 * p8;
    } else {
#pragma unroll
        for (int n = 0; n < NST; n++) e[n] = __expf(dtv * A[n]);
    }
}

__device__ __forceinline__ bool load_A(float A[NST], const float* __restrict__ A_log, int d) {
    bool fast = true;
#pragma unroll
    for (int n = 0; n < NST; n++) {
        A[n] = -expf(A_log[d * NST + n]);
        fast = fast && (fabsf(A[n] + (float)(n + 1)) <= 1e-3f * (float)(n + 1));
    }
    return fast;
}

// ---------------- fused selective scan (decoupled lookback) -------------------
// Phase A: local scan from h0=0, y_local = C.h_local + D*u (bf16 in smem);
// publish (E, H) + flag. Fold: wait predecessors, h0 = fold(E_i, H_i).
// Correction: y = (y_local + C.(P_t o h0)) * silu(z), P_t = exp(A * prefix dt).
#define SCAN_SMEM (CLEN * 32 * 4 + CLEN * 128 * 2)   // 16KB + 32KB = 49152

__global__ __launch_bounds__(128)
void scan_fused_kernel(const bf16* __restrict__ dt,
                       const bf16* __restrict__ u,
                       const float* __restrict__ xdbl,
                       const bf16* __restrict__ xz,
                       const float* __restrict__ A_log,
                       const float* __restrict__ Dv,
                       float* __restrict__ cE,
                       float* __restrict__ cH,
                       int* __restrict__ flags,
                       bf16* __restrict__ ybf) {
    extern __shared__ char sm[];
    float* sBC = (float*)sm;                        // CLEN*32 fp32
    bf16*  yloc = (bf16*)(sm + CLEN * 32 * 4);      // CLEN*128 bf16
    const int tid = threadIdx.x;
    const int d = blockIdx.x * 128 + tid;
    const int c = blockIdx.y;
    const int b = blockIdx.z;
    const int row0 = b * Lsz + c * CLEN;
    const int fbase = (b * NDBLK + blockIdx.x) * NC;

    for (int i = tid; i < CLEN * 32; i += 128)
        sBC[i] = xdbl[(size_t)(row0 + (i >> 5)) * XDBLW + DTR + (i & 31)];
    __syncthreads();

    float A[NST];
    bool fast = load_A(A, A_log, d);
    float h[NST];
#pragma unroll
    for (int n = 0; n < NST; n++) h[n] = 0.f;
    float sdt = 0.f;
    const float Dd = Dv[d];

    // ---- phase A: local scan ----
#pragma unroll 2
    for (int t = 0; t < CLEN; t++) {
        const int row = row0 + t;
        float dtv = __bfloat162float(dt[(size_t)row * DI + d]);
        float uv  = __bfloat162float(u [(size_t)row * DI + d]);
        float e[NST];
        compute_e(e, dtv, A, fast);
        float dtu = dtv * uv;
        sdt += dtv;
        const float* B = &sBC[t * 32];
        const float* C = &sBC[t * 32 + 16];
        float yl = Dd * uv;
#pragma unroll
        for (int n = 0; n < NST; n++) {
            h[n] = fmaf(h[n], e[n], dtu * B[n]);
            yl   = fmaf(h[n], C[n], yl);
        }
        yloc[t * 128 + tid] = __float2bfloat16(yl);
    }

    // ---- publish (E, H) + flag (threadFenceReduction pattern) ----
    {
        float E[NST];
        compute_e(E, sdt, A, fast);
        size_t base = ((size_t)(b * NC + c) * DI + d) * NST;
#pragma unroll
        for (int n = 0; n < NST; n++) { cE[base + n] = E[n]; cH[base + n] = h[n]; }
    }
    __threadfence();
    __syncthreads();
    if (tid == 0) atomicExch(&flags[fbase + c], 1);

    // ---- fold predecessors' states into h0 ----
    float h0[NST];
#pragma unroll
    for (int n = 0; n < NST; n++) h0[n] = 0.f;
    for (int i = 0; i < c; i++) {
        if (tid == 0) {
            while (atomicAdd(&flags[fbase + i], 0) == 0) __nanosleep(64);
        }
        __syncthreads();
        size_t ib = ((size_t)(b * NC + i) * DI + d) * NST;
#pragma unroll
        for (int n = 0; n < NST; n++)
            h0[n] = fmaf(cE[ib + n], h0[n], cH[ib + n]);
    }

    // ---- correction + gate ----
    float sdt2 = 0.f;
#pragma unroll 2
    for (int t = 0; t < CLEN; t++) {
        const int row = row0 + t;
        float dtv = __bfloat162float(dt[(size_t)row * DI + d]);
        sdt2 += dtv;
        float corr = 0.f;
        if (c > 0) {
            float P[NST];
            compute_e(P, sdt2, A, fast);
            const float* C = &sBC[t * 32 + 16];
#pragma unroll
            for (int n = 0; n < NST; n++)
                corr = fmaf(P[n] * h0[n], C[n], corr);
        }
        float zv = __bfloat162float(xz[(size_t)row * (2 * DI) + DI + d]);
        float yl = __bfloat162float(yloc[t * 128 + tid]);
        ybf[(size_t)row * DI + d] = __float2bfloat16((yl + corr) * fsilu(zv));
    }
}

// ---------------- out_proj partial sum + residual + LayerNorm ------------------
__global__ void ln_kernel(const float* __restrict__ pre,    // 2 partials stacked
                          const float* __restrict__ resid,
                          const float* __restrict__ w,
                          const float* __restrict__ bb,
                          float* __restrict__ out) {
    const int row = blockIdx.x;
    const int tid = threadIdx.x;
    __shared__ float vbuf[DM];
    __shared__ float ws[8], w2s[8];
    __shared__ float s_mu, s_inv;
    const size_t S = (size_t)MROWS * DM;
    float s = 0.f, s2 = 0.f;
    for (int i = tid; i < DM; i += blockDim.x) {
        size_t o = (size_t)row * DM + i;
        float v = pre[o] + pre[o + S] + resid[o];
        vbuf[i] = v;
        s += v; s2 += v * v;
    }
#pragma unroll
    for (int o = 16; o; o >>= 1) {
        s  += __shfl_xor_sync(0xffffffffu, s,  o);
        s2 += __shfl_xor_sync(0xffffffffu, s2, o);
    }
    int wid = tid >> 5, lane = tid & 31;
    if (lane == 0) { ws[wid] = s; w2s[wid] = s2; }
    __syncthreads();
    if (tid == 0) {
        float S1 = 0.f, S2 = 0.f;
        for (int i = 0; i < 8; i++) { S1 += ws[i]; S2 += w2s[i]; }
        float mu  = S1 / (float)DM;
        float var = S2 / (float)DM - mu * mu;
        s_mu = mu;
        s_inv = rsqrtf(var + 1e-5f);
    }
    __syncthreads();
    float mu = s_mu, inv = s_inv;
    for (int i = tid; i < DM; i += blockDim.x)
        out[(size_t)row * DM + i] = (vbuf[i] - mu) * inv * w[i] + bb[i];
}

// ---------------- launch ----------------------------------------------------
static float* sym_ptr(const void* symbol) {
    void* p = nullptr;
    cudaGetSymbolAddress(&p, symbol);
    return (float*)p;
}
static bf16* sym_ptr_bf(const void* symbol) {
    void* p = nullptr;
    cudaGetSymbolAddress(&p, symbol);
    return (bf16*)p;
}
static int* sym_ptr_i(const void* symbol) {
    void* p = nullptr;
    cudaGetSymbolAddress(&p, symbol);
    return (int*)p;
}

extern "C" void kernel_launch(void* const* d_in, const int* in_sizes, int n_in,
                              void* d_out, int out_size) {
    const float* x         = (const float*)d_in[0];
    const float* in_proj_w = (const float*)d_in[1];
    const float* conv_w    = (const float*)d_in[2];
    const float* conv_b    = (const float*)d_in[3];
    const float* x_proj_w  = (const float*)d_in[4];
    const float* dt_proj_w = (const float*)d_in[5];
    const float* dt_proj_b = (const float*)d_in[6];
    const float* A_log     = (const float*)d_in[7];
    const float* Dv        = (const float*)d_in[8];
    const float* out_proj_w= (const float*)d_in[9];
    const float* ln_w      = (const float*)d_in[10];
    const float* ln_b      = (const float*)d_in[11];
    float* out = (float*)d_out;

    bf16*  xz    = sym_ptr_bf(g_xz);
    bf16*  ubf   = sym_ptr_bf(g_ubf);
    float* xdbl  = sym_ptr(g_xdbl);
    float* xpp   = sym_ptr(g_xpp);
    bf16*  dtbf  = sym_ptr_bf(g_dtbf);
    bf16*  ybf   = sym_ptr_bf(g_ybf);
    float* opp   = sym_ptr(g_opp);
    float* cE    = sym_ptr(g_cE);
    float* cH    = sym_ptr(g_cH);
    int*   flags = sym_ptr_i(g_flags);
    bf16* xbf    = sym_ptr_bf(g_xbf);
    bf16* xdblbf = sym_ptr_bf(g_xdblbf);
    bf16* wip    = sym_ptr_bf(g_wip);
    bf16* wxp    = sym_ptr_bf(g_wxp);
    bf16* wdt    = sym_ptr_bf(g_wdt);
    bf16* wop    = sym_ptr_bf(g_wop);

    const int M = MROWS;

    static int attr_done = 0;
    if (!attr_done) {
        cudaFuncSetAttribute(gemm_bf16_kernel<0, 1, 1>,
                             cudaFuncAttributeMaxDynamicSharedMemorySize, GSMEM);
        cudaFuncSetAttribute(gemm_bf16_kernel<0, XSPK, 0>,
                             cudaFuncAttributeMaxDynamicSharedMemorySize, GSMEM);
        cudaFuncSetAttribute(gemm_bf16_kernel<1, 1, 1>,
                             cudaFuncAttributeMaxDynamicSharedMemorySize, GSMEM);
        cudaFuncSetAttribute(gemm_bf16_kernel<0, 2, 0>,
                             cudaFuncAttributeMaxDynamicSharedMemorySize, GSMEM);
        cudaFuncSetAttribute(scan_fused_kernel,
                             cudaFuncAttributeMaxDynamicSharedMemorySize, SCAN_SMEM);
        attr_done = 1;
    }

    // 0) conversions + flag reset in ONE kernel
    convert_all_kernel<<<(CN5 + 255) / 256, 256>>>(
        x, in_proj_w, x_proj_w, out_proj_w, dt_proj_w,
        xbf, wip, wxp, wop, wdt, flags);

    // 1) in_proj: xz[M, 3072] = x @ in_proj_w^T  (bf16 out)
    gemm_bf16_kernel<0, 1, 1><<<dim3((2 * DI) / 128, M / 128, 1), 256, GSMEM>>>(
        xbf, DM, wip, DM, nullptr, xz, M, 2 * DI, DM);

    // 2) causal depthwise conv + SiLU -> ubf
    conv_silu_kernel<<<dim3(DI / 32, Lsz / 64, Bsz), 256>>>(xz, conv_w, conv_b, ubf);

    // 3) x_proj: xdbl[M, 80] = u @ x_proj_w^T (split-K = 8)
    gemm_bf16_kernel<0, XSPK, 0><<<dim3(1, M / 128, XSPK), 256, GSMEM>>>(
        ubf, DI, wxp, DI, nullptr, xpp, M, XDBLW, DI);
    xp_reduce_kernel<<<(M * XDBLW + 255) / 256, 256>>>(xpp, xdbl, xdblbf);

    // 4) dt[M,1536] = softplus(dtl @ dt_proj_w^T + b)  (bf16 out; K padded 48->64)
    gemm_bf16_kernel<1, 1, 1><<<dim3(DI / 128, M / 128, 1), 256, GSMEM>>>(
        xdblbf, XDBLW, wdt, KDT, dt_proj_b, dtbf, M, DI, KDT);

    // 5) fused chunk-parallel selective scan + gate -> ybf
    scan_fused_kernel<<<dim3(NDBLK, NC, Bsz), 128, SCAN_SMEM>>>(
        dtbf, ubf, xdbl, xz, A_log, Dv, cE, cH, flags, ybf);

    // 6) out_proj: opp[z][M,768] = y @ out_proj_w^T (split-K = 2)
    gemm_bf16_kernel<0, 2, 0><<<dim3(DM / 128, M / 128, 2), 256, GSMEM>>>(
        ybf, DI, wop, DI, nullptr, opp, M, DM, DI);

    // 7) partial-sum + residual + LayerNorm -> d_out
    ln_kernel<<<M, 256>>>(opp, x, ln_w, ln_b, out);
}

// round 16
// speedup vs baseline: 1.0017x; 1.0009x over previous
#include <cuda_runtime.h>
#include <cuda_bf16.h>
#include <math.h>
#include <stdint.h>

#define Bsz   2
#define Lsz   2048
#define DM    768
#define DI    1536
#define NST   16
#define DTR   48
#define XDBLW 80          // DTR + 2*NST
#define MROWS (Bsz*Lsz)   // 4096
#define NC    16          // scan chunks
#define CLEN  (Lsz/NC)    // 128
#define KDT   64          // padded K for dt GEMM
#define XSPK  8           // x_proj split-K
#define NDBLK (DI/128)    // 12 scan d-blocks
#define FLAGN (Bsz * NDBLK * NC)   // 384

typedef __nv_bfloat16 bf16;

// ---------------- scratch (device globals; no allocs allowed) ----------------
__device__ bf16  g_xz  [MROWS * 2 * DI];       // in_proj output: u_raw | z (bf16)
__device__ bf16  g_ubf [MROWS * DI];           // post conv+silu (bf16)
__device__ float g_xdbl[MROWS * XDBLW];        // dtl | B | C (fp32, scan B/C)
__device__ float g_xpp [XSPK * MROWS * XDBLW]; // x_proj split-K partials
__device__ bf16  g_dtbf[MROWS * DI];           // softplus(dt) (bf16)
__device__ bf16  g_ybf [MROWS * DI];           // gated scan output (bf16)
__device__ float g_opp [2 * MROWS * DM];       // out_proj split-K partials
__device__ float g_cE  [Bsz * NC * DI * NST];  // per-chunk E
__device__ float g_cH  [Bsz * NC * DI * NST];  // per-chunk H (from h0=0)
__device__ int   g_flags[FLAGN];               // scan lookback flags
// bf16 mirrors for tensor-core GEMM operands
__device__ bf16 g_xbf   [MROWS * DM];          // x
__device__ bf16 g_xdblbf[MROWS * XDBLW];       // xdbl
__device__ bf16 g_wip   [2 * DI * DM];         // in_proj_w
__device__ bf16 g_wxp   [XDBLW * DI];          // x_proj_w
__device__ bf16 g_wdt   [DI * KDT];            // dt_proj_w zero-padded 48->64
__device__ bf16 g_wop   [DM * DI];             // out_proj_w

// ---------------- helpers ----------------------------------------------------
__device__ __forceinline__ void mma_bf16(float* c, const uint32_t* a, const uint32_t* b) {
    asm volatile(
        "mma.sync.aligned.m16n8k16.row.col.f32.bf16.bf16.f32 "
        "{%0,%1,%2,%3}, {%4,%5,%6,%7}, {%8,%9}, {%0,%1,%2,%3};\n"
        : "+f"(c[0]), "+f"(c[1]), "+f"(c[2]), "+f"(c[3])
        : "r"(a[0]), "r"(a[1]), "r"(a[2]), "r"(a[3]), "r"(b[0]), "r"(b[1]));
}

__device__ __forceinline__ void ldsm4(uint32_t* r, uint32_t addr) {
    asm volatile("ldmatrix.sync.aligned.m8n8.x4.shared.b16 {%0,%1,%2,%3}, [%4];"
                 : "=r"(r[0]), "=r"(r[1]), "=r"(r[2]), "=r"(r[3]) : "r"(addr));
}

__device__ __forceinline__ float fsilu(float x) {
    return x * __fdividef(1.f, 1.f + __expf(-x));
}

__device__ __forceinline__ void cp16u(uint32_t sdst, const void* gsrc, bool pred) {
    int sz = pred ? 16 : 0;                       // src-size 0 -> zero-fill
    asm volatile("cp.async.cg.shared.global [%0], [%1], 16, %2;\n"
                 :: "r"(sdst), "l"(gsrc), "r"(sz));
}
__device__ __forceinline__ void cp_commit() { asm volatile("cp.async.commit_group;\n"); }
template<int N_>
__device__ __forceinline__ void cp_wait() { asm volatile("cp.async.wait_group %0;\n" :: "n"(N_)); }

// ---------------- fused fp32 -> bf16 conversion + flag reset ------------------
__device__ __forceinline__ void cvt2(const float* __restrict__ s, bf16* __restrict__ d, int i) {
    float2 v = ((const float2*)s)[i];
    ((__nv_bfloat162*)d)[i] = __float22bfloat162_rn(v);
}

#define CN0 (MROWS * DM / 2)              // x
#define CN1 (CN0 + DI * DM)               // + in_proj_w
#define CN2 (CN1 + XDBLW * DI / 2)        // + x_proj_w
#define CN3 (CN2 + DM * DI / 2)           // + out_proj_w
#define CN4 (CN3 + DI * 32)               // + dt pad units
#define CN5 (CN4 + FLAGN)                 // + scan flags

__global__ void convert_all_kernel(const float* __restrict__ x,
                                   const float* __restrict__ wip_f,
                                   const float* __restrict__ wxp_f,
                                   const float* __restrict__ wop_f,
                                   const float* __restrict__ wdt_f,
                                   bf16* __restrict__ xbf, bf16* __restrict__ wip,
                                   bf16* __restrict__ wxp, bf16* __restrict__ wop,
                                   bf16* __restrict__ wdt, int* __restrict__ flags) {
    int i = blockIdx.x * blockDim.x + threadIdx.x;
    if (i < CN0)      cvt2(x, xbf, i);
    else if (i < CN1) cvt2(wip_f, wip, i - CN0);
    else if (i < CN2) cvt2(wxp_f, wxp, i - CN1);
    else if (i < CN3) cvt2(wop_f, wop, i - CN2);
    else if (i < CN4) {
        int j = i - CN3;                  // unit over DI x 32 (pairs of cols)
        int r = j >> 5, c2 = j & 31;
        float v0 = 0.f, v1 = 0.f;
        if (c2 < 24) { v0 = wdt_f[r * DTR + 2 * c2]; v1 = wdt_f[r * DTR + 2 * c2 + 1]; }
        ((__nv_bfloat162*)wdt)[r * 32 + c2] = __float22bfloat162_rn(make_float2(v0, v1));
    } else if (i < CN5) flags[i - CN4] = 0;
}

// ---------------- pipelined bf16 HMMA GEMM (ldmatrix, BK=64, 3-stage) ---------
// Single __syncthreads per mainloop iteration (classic multistage invariant).
#define SPB   72                 // smem row pitch in bf16 (64 data + 8 pad)
#define NSTG  3
#define ASTG  (128 * SPB * 2)    // 18432 bytes per stage per array
#define GSMEM (2 * NSTG * ASTG)  // 110592 bytes total

template<int EPI, int SPLITK, int OBF>
__global__ __launch_bounds__(256, 2)
void gemm_bf16_kernel(const bf16* __restrict__ A, int lda,
                      const bf16* __restrict__ W, int ldw,
                      const float* __restrict__ bias,
                      void* __restrict__ Cv,
                      int M, int N, int K) {
    extern __shared__ char dsm[];
    const uint32_t smemu = (uint32_t)__cvta_generic_to_shared(dsm);
    const int tx   = threadIdx.x;
    const int lane = tx & 31;
    const int wid  = tx >> 5;
    const int warp_m = wid & 3;
    const int warp_n = wid >> 2;
    const int brow = blockIdx.y * 128;
    const int bcol = blockIdx.x * 128;
    const int q = lane & 3;
    const int g = lane >> 2;

    const int kn = K / SPLITK;
    const int kBegin = blockIdx.z * kn;
    const int KT = kn / 64;

    int rS[4], eS[4];
#pragma unroll
    for (int i = 0; i < 4; i++) {
        int c = tx + i * 256;
        rS[i] = c >> 3;
        eS[i] = (c & 7) << 3;
    }

    uint32_t offA[2];
#pragma unroll
    for (int i = 0; i < 2; i++)
        offA[i] = (uint32_t)(((warp_m * 32 + i * 16 + (lane & 15)) * SPB
                              + ((lane >> 4) << 3)) * 2);
    uint32_t offB[4];
#pragma unroll
    for (int jj = 0; jj < 4; jj++)
        offB[jj] = (uint32_t)(((warp_n * 64 + jj * 16 + (lane & 7) + ((lane >> 4) << 3)) * SPB
                               + (((lane >> 3) & 1) << 3)) * 2);

    float acc[2][8][4];
#pragma unroll
    for (int i = 0; i < 2; i++)
#pragma unroll
        for (int j = 0; j < 8; j++)
#pragma unroll
            for (int v = 0; v < 4; v++) acc[i][j][v] = 0.f;

    auto stage = [&](int kt) {
        int st = kt % NSTG;
        uint32_t ab = smemu + st * ASTG;
        uint32_t bb = smemu + NSTG * ASTG + st * ASTG;
        int k0 = kBegin + kt * 64;
#pragma unroll
        for (int i = 0; i < 4; i++) {
            cp16u(ab + (uint32_t)((rS[i] * SPB + eS[i]) * 2),
                  A + (size_t)(brow + rS[i]) * lda + k0 + eS[i], true);
            cp16u(bb + (uint32_t)((rS[i] * SPB + eS[i]) * 2),
                  W + (size_t)(bcol + rS[i]) * ldw + k0 + eS[i], (bcol + rS[i]) < N);
        }
        cp_commit();
    };

#pragma unroll
    for (int s = 0; s < NSTG - 1; s++) {
        if (s < KT) stage(s); else cp_commit();
    }

    for (int kt = 0; kt < KT; kt++) {
        cp_wait<NSTG - 2>();
        __syncthreads();
        const int st = kt % NSTG;
        const uint32_t ab = smemu + st * ASTG;
        const uint32_t bb = smemu + NSTG * ASTG + st * ASTG;
#pragma unroll
        for (int kk = 0; kk < 64; kk += 16) {
            uint32_t af[2][4], bfr[4][4];
            ldsm4(af[0], ab + offA[0] + kk * 2);
            ldsm4(af[1], ab + offA[1] + kk * 2);
#pragma unroll
            for (int jj = 0; jj < 4; jj++)
                ldsm4(bfr[jj], bb + offB[jj] + kk * 2);
#pragma unroll
            for (int i = 0; i < 2; i++)
#pragma unroll
                for (int j = 0; j < 8; j++) {
                    const uint32_t* bp = &bfr[j >> 1][(j & 1) << 1];
                    mma_bf16(acc[i][j], af[i], bp);
                }
        }
        // buffer (kt+NSTG-1)%NSTG was consumed at iteration kt-1; the sync at
        // the top of this iteration proves all warps finished it -> safe.
        if (kt + NSTG - 1 < KT) stage(kt + NSTG - 1); else cp_commit();
    }

    // epilogue
    float* Cf = (float*)Cv + (size_t)blockIdx.z * M * N;
    bf16*  Cb = (bf16*)Cv;
#pragma unroll
    for (int i = 0; i < 2; i++) {
#pragma unroll
        for (int j = 0; j < 8; j++) {
            int r0w = brow + warp_m * 32 + i * 16 + g;
            int c0w = bcol + warp_n * 64 + j * 8 + 2 * q;
            if (c0w >= N) continue;
            float v0 = acc[i][j][0], v1 = acc[i][j][1];
            float v2 = acc[i][j][2], v3 = acc[i][j][3];
            if (EPI == 1) {
                float b0 = bias[c0w], b1 = bias[c0w + 1];
                v0 += b0; v1 += b1; v2 += b0; v3 += b1;
                v0 = (v0 > 15.f) ? v0 : __logf(1.f + __expf(v0));
                v1 = (v1 > 15.f) ? v1 : __logf(1.f + __expf(v1));
                v2 = (v2 > 15.f) ? v2 : __logf(1.f + __expf(v2));
                v3 = (v3 > 15.f) ? v3 : __logf(1.f + __expf(v3));
            }
            if (OBF) {
                *(__nv_bfloat162*)(Cb + (size_t)r0w * N + c0w) =
                    __float22bfloat162_rn(make_float2(v0, v1));
                *(__nv_bfloat162*)(Cb + (size_t)(r0w + 8) * N + c0w) =
                    __float22bfloat162_rn(make_float2(v2, v3));
            } else {
                *(float2*)(Cf + (size_t)r0w * N + c0w)       = make_float2(v0, v1);
                *(float2*)(Cf + (size_t)(r0w + 8) * N + c0w) = make_float2(v2, v3);
            }
        }
    }
}

// ---------------- x_proj split-K reduce (fp32 + bf16 outputs) ----------------
__global__ void xp_reduce_kernel(const float* __restrict__ p,
                                 float* __restrict__ o,
                                 bf16* __restrict__ obf) {
    int i = blockIdx.x * blockDim.x + threadIdx.x;
    const int S = MROWS * XDBLW;
    if (i >= S) return;
    float v = 0.f;
#pragma unroll
    for (int k = 0; k < XSPK; k++) v += p[i + (size_t)k * S];
    o[i] = v;
    obf[i] = __float2bfloat16(v);
}

// ---------------- causal depthwise conv (k=4) + bias + SiLU ------------------
__global__ __launch_bounds__(256)
void conv_silu_kernel(const bf16* __restrict__ xz,
                      const float* __restrict__ cw,
                      const float* __restrict__ cb,
                      bf16* __restrict__ u) {
    const int lane = threadIdx.x & 31;
    const int w    = threadIdx.x >> 5;
    const int d  = blockIdx.x * 32 + lane;
    const int l0 = (blockIdx.y * 8 + w) * 8;
    const int b  = blockIdx.z;

    float4 wk = ((const float4*)cw)[d];
    float bias = cb[d];

    float xv[11];
#pragma unroll
    for (int i = 0; i < 11; i++) {
        int ls = l0 - 3 + i;
        xv[i] = (ls >= 0)
            ? __bfloat162float(xz[(size_t)(b * Lsz + ls) * (2 * DI) + d]) : 0.f;
    }
#pragma unroll
    for (int j = 0; j < 8; j++) {
        float acc = bias;
        acc = fmaf(wk.x, xv[j],     acc);
        acc = fmaf(wk.y, xv[j + 1], acc);
        acc = fmaf(wk.z, xv[j + 2], acc);
        acc = fmaf(wk.w, xv[j + 3], acc);
        u[(size_t)(b * Lsz + l0 + j) * DI + d] = __float2bfloat16(fsilu(acc));
    }
}

// ---------------- scan: shared pieces ----------------------------------------
__device__ __forceinline__ void compute_e(float e[NST], float dtv,
                                          const float A[NST], bool fast) {
    if (fast) {
        float p  = __expf(-dtv);
        float p2 = p * p, p4 = p2 * p2, p8 = p4 * p4;
        e[0]  = p;        e[1]  = p2;       e[2]  = p2 * p;   e[3]  = p4;
        e[4]  = p4 * p;   e[5]  = p4 * p2;  e[6]  = p4 * e[2];e[7]  = p8;
        e[8]  = p8 * p;   e[9]  = p8 * p2;  e[10] = p8 * e[2];e[11] = p8 * p4;
        e[12] = p8 * e[4];e[13] = p8 * e[5];e[14] = p8 * e[6];e[15] = p8 * p8;
    } else {
#pragma unroll
        for (int n = 0; n < NST; n++) e[n] = __expf(dtv * A[n]);
    }
}

__device__ __forceinline__ bool load_A(float A[NST], const float* __restrict__ A_log, int d) {
    bool fast = true;
#pragma unroll
    for (int n = 0; n < NST; n++) {
        A[n] = -expf(A_log[d * NST + n]);
        fast = fast && (fabsf(A[n] + (float)(n + 1)) <= 1e-3f * (float)(n + 1));
    }
    return fast;
}

// ---------------- fused selective scan (decoupled lookback) -------------------
// Phase A: local scan from h0=0, y_local = C.h_local + D*u (bf16 in smem);
// publish (E, H) + flag. Fold: wait predecessors, h0 = fold(E_i, H_i).
// Correction: y = (y_local + C.(P_t o h0)) * silu(z), P_t = exp(A * prefix dt).
#define SCAN_SMEM (CLEN * 32 * 4 + CLEN * 128 * 2)   // 16KB + 32KB = 49152

__global__ __launch_bounds__(128)
void scan_fused_kernel(const bf16* __restrict__ dt,
                       const bf16* __restrict__ u,
                       const float* __restrict__ xdbl,
                       const bf16* __restrict__ xz,
                       const float* __restrict__ A_log,
                       const float* __restrict__ Dv,
                       float* __restrict__ cE,
                       float* __restrict__ cH,
                       int* __restrict__ flags,
                       bf16* __restrict__ ybf) {
    extern __shared__ char sm[];
    float* sBC = (float*)sm;                        // CLEN*32 fp32
    bf16*  yloc = (bf16*)(sm + CLEN * 32 * 4);      // CLEN*128 bf16
    const int tid = threadIdx.x;
    const int d = blockIdx.x * 128 + tid;
    const int c = blockIdx.y;
    const int b = blockIdx.z;
    const int row0 = b * Lsz + c * CLEN;
    const int fbase = (b * NDBLK + blockIdx.x) * NC;

    for (int i = tid; i < CLEN * 32; i += 128)
        sBC[i] = xdbl[(size_t)(row0 + (i >> 5)) * XDBLW + DTR + (i & 31)];
    __syncthreads();

    float A[NST];
    bool fast = load_A(A, A_log, d);
    float h[NST];
#pragma unroll
    for (int n = 0; n < NST; n++) h[n] = 0.f;
    float sdt = 0.f;
    const float Dd = Dv[d];

    // ---- phase A: local scan ----
#pragma unroll 2
    for (int t = 0; t < CLEN; t++) {
        const int row = row0 + t;
        float dtv = __bfloat162float(dt[(size_t)row * DI + d]);
        float uv  = __bfloat162float(u [(size_t)row * DI + d]);
        float e[NST];
        compute_e(e, dtv, A, fast);
        float dtu = dtv * uv;
        sdt += dtv;
        const float* B = &sBC[t * 32];
        const float* C = &sBC[t * 32 + 16];
        float yl = Dd * uv;
#pragma unroll
        for (int n = 0; n < NST; n++) {
            h[n] = fmaf(h[n], e[n], dtu * B[n]);
            yl   = fmaf(h[n], C[n], yl);
        }
        yloc[t * 128 + tid] = __float2bfloat16(yl);
    }

    // ---- publish (E, H) + flag (threadFenceReduction pattern) ----
    {
        float E[NST];
        compute_e(E, sdt, A, fast);
        size_t base = ((size_t)(b * NC + c) * DI + d) * NST;
#pragma unroll
        for (int n = 0; n < NST; n++) { cE[base + n] = E[n]; cH[base + n] = h[n]; }
    }
    __threadfence();
    __syncthreads();
    if (tid == 0) atomicExch(&flags[fbase + c], 1);

    // ---- fold predecessors' states into h0 ----
    float h0[NST];
#pragma unroll
    for (int n = 0; n < NST; n++) h0[n] = 0.f;
    for (int i = 0; i < c; i++) {
        if (tid == 0) {
            while (atomicAdd(&flags[fbase + i], 0) == 0) __nanosleep(64);
        }
        __syncthreads();
        size_t ib = ((size_t)(b * NC + i) * DI + d) * NST;
#pragma unroll
        for (int n = 0; n < NST; n++)
            h0[n] = fmaf(cE[ib + n], h0[n], cH[ib + n]);
    }

    // ---- correction + gate ----
    float sdt2 = 0.f;
#pragma unroll 2
    for (int t = 0; t < CLEN; t++) {
        const int row = row0 + t;
        float dtv = __bfloat162float(dt[(size_t)row * DI + d]);
        sdt2 += dtv;
        float corr = 0.f;
        if (c > 0) {
            float P[NST];
            compute_e(P, sdt2, A, fast);
            const float* C = &sBC[t * 32 + 16];
#pragma unroll
            for (int n = 0; n < NST; n++)
                corr = fmaf(P[n] * h0[n], C[n], corr);
        }
        float zv = __bfloat162float(xz[(size_t)row * (2 * DI) + DI + d]);
        float yl = __bfloat162float(yloc[t * 128 + tid]);
        ybf[(size_t)row * DI + d] = __float2bfloat16((yl + corr) * fsilu(zv));
    }
}

// ---------------- out_proj partial sum + residual + LayerNorm ------------------
__global__ void ln_kernel(const float* __restrict__ pre,    // 2 partials stacked
                          const float* __restrict__ resid,
                          const float* __restrict__ w,
                          const float* __restrict__ bb,
                          float* __restrict__ out) {
    const int row = blockIdx.x;
    const int tid = threadIdx.x;
    __shared__ float vbuf[DM];
    __shared__ float ws[8], w2s[8];
    __shared__ float s_mu, s_inv;
    const size_t S = (size_t)MROWS * DM;
    float s = 0.f, s2 = 0.f;
    for (int i = tid; i < DM; i += blockDim.x) {
        size_t o = (size_t)row * DM + i;
        float v = pre[o] + pre[o + S] + resid[o];
        vbuf[i] = v;
        s += v; s2 += v * v;
    }
#pragma unroll
    for (int o = 16; o; o >>= 1) {
        s  += __shfl_xor_sync(0xffffffffu, s,  o);
        s2 += __shfl_xor_sync(0xffffffffu, s2, o);
    }
    int wid = tid >> 5, lane = tid & 31;
    if (lane == 0) { ws[wid] = s; w2s[wid] = s2; }
    __syncthreads();
    if (tid == 0) {
        float S1 = 0.f, S2 = 0.f;
        for (int i = 0; i < 8; i++) { S1 += ws[i]; S2 += w2s[i]; }
        float mu  = S1 / (float)DM;
        float var = S2 / (float)DM - mu * mu;
        s_mu = mu;
        s_inv = rsqrtf(var + 1e-5f);
    }
    __syncthreads();
    float mu = s_mu, inv = s_inv;
    for (int i = tid; i < DM; i += blockDim.x)
        out[(size_t)row * DM + i] = (vbuf[i] - mu) * inv * w[i] + bb[i];
}

// ---------------- launch ----------------------------------------------------
static float* sym_ptr(const void* symbol) {
    void* p = nullptr;
    cudaGetSymbolAddress(&p, symbol);
    return (float*)p;
}
static bf16* sym_ptr_bf(const void* symbol) {
    void* p = nullptr;
    cudaGetSymbolAddress(&p, symbol);
    return (bf16*)p;
}
static int* sym_ptr_i(const void* symbol) {
    void* p = nullptr;
    cudaGetSymbolAddress(&p, symbol);
    return (int*)p;
}

extern "C" void kernel_launch(void* const* d_in, const int* in_sizes, int n_in,
                              void* d_out, int out_size) {
    const float* x         = (const float*)d_in[0];
    const float* in_proj_w = (const float*)d_in[1];
    const float* conv_w    = (const float*)d_in[2];
    const float* conv_b    = (const float*)d_in[3];
    const float* x_proj_w  = (const float*)d_in[4];
    const float* dt_proj_w = (const float*)d_in[5];
    const float* dt_proj_b = (const float*)d_in[6];
    const float* A_log     = (const float*)d_in[7];
    const float* Dv        = (const float*)d_in[8];
    const float* out_proj_w= (const float*)d_in[9];
    const float* ln_w      = (const float*)d_in[10];
    const float* ln_b      = (const float*)d_in[11];
    float* out = (float*)d_out;

    bf16*  xz    = sym_ptr_bf(g_xz);
    bf16*  ubf   = sym_ptr_bf(g_ubf);
    float* xdbl  = sym_ptr(g_xdbl);
    float* xpp   = sym_ptr(g_xpp);
    bf16*  dtbf  = sym_ptr_bf(g_dtbf);
    bf16*  ybf   = sym_ptr_bf(g_ybf);
    float* opp   = sym_ptr(g_opp);
    float* cE    = sym_ptr(g_cE);
    float* cH    = sym_ptr(g_cH);
    int*   flags = sym_ptr_i(g_flags);
    bf16* xbf    = sym_ptr_bf(g_xbf);
    bf16* xdblbf = sym_ptr_bf(g_xdblbf);
    bf16* wip    = sym_ptr_bf(g_wip);
    bf16* wxp    = sym_ptr_bf(g_wxp);
    bf16* wdt    = sym_ptr_bf(g_wdt);
    bf16* wop    = sym_ptr_bf(g_wop);

    const int M = MROWS;

    static int attr_done = 0;
    if (!attr_done) {
        cudaFuncSetAttribute(gemm_bf16_kernel<0, 1, 1>,
                             cudaFuncAttributeMaxDynamicSharedMemorySize, GSMEM);
        cudaFuncSetAttribute(gemm_bf16_kernel<0, XSPK, 0>,
                             cudaFuncAttributeMaxDynamicSharedMemorySize, GSMEM);
        cudaFuncSetAttribute(gemm_bf16_kernel<1, 1, 1>,
                             cudaFuncAttributeMaxDynamicSharedMemorySize, GSMEM);
        cudaFuncSetAttribute(gemm_bf16_kernel<0, 2, 0>,
                             cudaFuncAttributeMaxDynamicSharedMemorySize, GSMEM);
        cudaFuncSetAttribute(scan_fused_kernel,
                             cudaFuncAttributeMaxDynamicSharedMemorySize, SCAN_SMEM);
        attr_done = 1;
    }

    // 0) conversions + flag reset in ONE kernel
    convert_all_kernel<<<(CN5 + 255) / 256, 256>>>(
        x, in_proj_w, x_proj_w, out_proj_w, dt_proj_w,
        xbf, wip, wxp, wop, wdt, flags);

    // 1) in_proj: xz[M, 3072] = x @ in_proj_w^T  (bf16 out)
    gemm_bf16_kernel<0, 1, 1><<<dim3((2 * DI) / 128, M / 128, 1), 256, GSMEM>>>(
        xbf, DM, wip, DM, nullptr, xz, M, 2 * DI, DM);

    // 2) causal depthwise conv + SiLU -> ubf
    conv_silu_kernel<<<dim3(DI / 32, Lsz / 64, Bsz), 256>>>(xz, conv_w, conv_b, ubf);

    // 3) x_proj: xdbl[M, 80] = u @ x_proj_w^T (split-K = 8)
    gemm_bf16_kernel<0, XSPK, 0><<<dim3(1, M / 128, XSPK), 256, GSMEM>>>(
        ubf, DI, wxp, DI, nullptr, xpp, M, XDBLW, DI);
    xp_reduce_kernel<<<(M * XDBLW + 255) / 256, 256>>>(xpp, xdbl, xdblbf);

    // 4) dt[M,1536] = softplus(dtl @ dt_proj_w^T + b)  (bf16 out; K padded 48->64)
    gemm_bf16_kernel<1, 1, 1><<<dim3(DI / 128, M / 128, 1), 256, GSMEM>>>(
        xdblbf, XDBLW, wdt, KDT, dt_proj_b, dtbf, M, DI, KDT);

    // 5) fused chunk-parallel selective scan + gate -> ybf
    scan_fused_kernel<<<dim3(NDBLK, NC, Bsz), 128, SCAN_SMEM>>>(
        dtbf, ubf, xdbl, xz, A_log, Dv, cE, cH, flags, ybf);

    // 6) out_proj: opp[z][M,768] = y @ out_proj_w^T (split-K = 2)
    gemm_bf16_kernel<0, 2, 0><<<dim3(DM / 128, M / 128, 2), 256, GSMEM>>>(
        ybf, DI, wop, DI, nullptr, opp, M, DM, DI);

    // 7) partial-sum + residual + LayerNorm -> d_out
    ln_kernel<<<M, 256>>>(opp, x, ln_w, ln_b, out);
}